// round 4
// baseline (speedup 1.0000x reference)
#include <cuda_runtime.h>
#include <math.h>

// ---------------- problem constants ----------------
#define SEQL  64
#define BATCH 64
#define HID   1024
#define EMBD  1024
#define VOCAB 32000
#define BH    (BATCH*HID)            // 65536
#define LOGITS_N ((size_t)SEQL*BATCH*VOCAB)
#define SQRTE 32.0f                  // sqrt(1024)

typedef unsigned long long u64;

// ---------------- packed f32x2 helpers ----------------
__device__ __forceinline__ u64 pk2(float lo, float hi){
    u64 r; asm("mov.b64 %0, {%1, %2};" : "=l"(r) : "f"(lo), "f"(hi)); return r;
}
__device__ __forceinline__ void fma2(u64 &d, u64 a, u64 b){
    asm("fma.rn.f32x2 %0, %1, %2, %0;" : "+l"(d) : "l"(a), "l"(b));
}
__device__ __forceinline__ float2 unpk2(u64 v){
    float2 f; asm("mov.b64 {%0, %1}, %2;" : "=f"(f.x), "=f"(f.y) : "l"(v)); return f;
}
__device__ __forceinline__ float sigmf(float x){ return 1.0f/(1.0f + expf(-x)); }

// ---------------- device scratch (no cudaMalloc allowed) ----------------
__device__ __align__(16) float g_Xin[SEQL*BH];      // x_t @ W_in^T for all t
__device__ __align__(16) float g_H[SEQL*BH];        // h1_t for all t
__device__ __align__(16) float g_prev0[BH];
__device__ __align__(16) float g_prev1[BH];
__device__ __align__(16) float g_r0pre[BH];
__device__ __align__(16) float g_f0pre[BH];
__device__ __align__(16) float g_h0pre[BH];
__device__ __align__(16) float g_rp0[BH];
__device__ __align__(16) float g_z0[BH];
__device__ __align__(16) float g_rp1[BH];
__device__ __align__(16) float g_z1[BH];
__device__ __align__(16) float g_part[48*BH];       // split-K partials

// ---------------- fp32 C = alpha*(A · Wᵀ) (+bias) tile core ----------------
// C[m,n] = alpha * sum_k A[m,k]*W[n,k] (+bias[n])
// Tile: BM x 128, BK=16; per-thread 8x8 fragment split 4+4 in each dim.
template<int BM, int NTH>
__device__ __forceinline__ void gemm_core(
    const float* __restrict__ A, int lda, int aRow0, const int* __restrict__ aMap,
    const float* __restrict__ W, int ldw, int wRow0,
    int k0, int kLen,
    float* __restrict__ C, int ldc, int cRow0, int cCol0,
    float alpha, const float* __restrict__ bias)
{
    constexpr int BN  = 128;
    constexpr int BKt = 16;
    constexpr int AF4   = (BM*BKt)/(4*NTH);
    constexpr int WF4   = (BN*BKt)/(4*NTH);
    constexpr int RSTEP = NTH/4;

    __shared__ __align__(16) float sA[BKt][BM];
    __shared__ __align__(16) float sW[BKt][BN];

    const int tid = threadIdx.x;
    const int lr  = tid >> 2;
    const int kq  = tid & 3;
    const int tx  = tid & 15;
    const int ty  = tid >> 4;

    const float* aPtr[AF4];
#pragma unroll
    for (int i = 0; i < AF4; i++){
        int r  = aRow0 + lr + i*RSTEP;
        int rr = aMap ? aMap[r] : r;
        aPtr[i] = A + (size_t)rr*lda + (k0 + kq*4);
    }
    const float* wPtr[WF4];
#pragma unroll
    for (int i = 0; i < WF4; i++)
        wPtr[i] = W + (size_t)(wRow0 + lr + i*RSTEP)*ldw + (k0 + kq*4);

    u64 acc[4][8];
#pragma unroll
    for (int p = 0; p < 4; p++)
#pragma unroll
        for (int n = 0; n < 8; n++) acc[p][n] = 0ull;

    for (int k = 0; k < kLen; k += BKt){
        float4 av[AF4], wv[WF4];
#pragma unroll
        for (int i = 0; i < AF4; i++) av[i] = *(const float4*)(aPtr[i] + k);
#pragma unroll
        for (int i = 0; i < WF4; i++) wv[i] = *(const float4*)(wPtr[i] + k);
        __syncthreads();    // previous tile fully consumed
#pragma unroll
        for (int i = 0; i < AF4; i++){
            int r = lr + i*RSTEP;
            sA[kq*4+0][r] = av[i].x; sA[kq*4+1][r] = av[i].y;
            sA[kq*4+2][r] = av[i].z; sA[kq*4+3][r] = av[i].w;
        }
#pragma unroll
        for (int i = 0; i < WF4; i++){
            int r = lr + i*RSTEP;
            sW[kq*4+0][r] = wv[i].x; sW[kq*4+1][r] = wv[i].y;
            sW[kq*4+2][r] = wv[i].z; sW[kq*4+3][r] = wv[i].w;
        }
        __syncthreads();
#pragma unroll
        for (int kk = 0; kk < BKt; kk++){
            float4 aL = *(const float4*)&sA[kk][ty*4];
            float4 aH = *(const float4*)&sA[kk][BM/2 + ty*4];
            u64 ap[4] = { pk2(aL.x,aL.y), pk2(aL.z,aL.w),
                          pk2(aH.x,aH.y), pk2(aH.z,aH.w) };
            float4 b0 = *(const float4*)&sW[kk][tx*4];
            float4 b1 = *(const float4*)&sW[kk][64 + tx*4];
            float bv[8] = {b0.x,b0.y,b0.z,b0.w,b1.x,b1.y,b1.z,b1.w};
#pragma unroll
            for (int n = 0; n < 8; n++){
                u64 bd = pk2(bv[n], bv[n]);
#pragma unroll
                for (int p = 0; p < 4; p++) fma2(acc[p][n], ap[p], bd);
            }
        }
    }

    float4 bb0 = make_float4(0.f,0.f,0.f,0.f), bb1 = bb0;
    if (bias){
        bb0 = *(const float4*)&bias[cCol0 + tx*4];
        bb1 = *(const float4*)&bias[cCol0 + 64 + tx*4];
    }
#pragma unroll
    for (int p = 0; p < 4; p++){
        float2 f0 = unpk2(acc[p][0]), f1 = unpk2(acc[p][1]);
        float2 f2 = unpk2(acc[p][2]), f3 = unpk2(acc[p][3]);
        float2 f4 = unpk2(acc[p][4]), f5 = unpk2(acc[p][5]);
        float2 f6 = unpk2(acc[p][6]), f7 = unpk2(acc[p][7]);
        int rloc = ((p < 2) ? 0 : BM/2) + ty*4 + (p & 1)*2;
        size_t base0 = (size_t)(cRow0 + rloc    )*ldc + cCol0 + tx*4;
        size_t base1 = (size_t)(cRow0 + rloc + 1)*ldc + cCol0 + tx*4;
        float4 vlo0 = make_float4(alpha*f0.x+bb0.x, alpha*f1.x+bb0.y, alpha*f2.x+bb0.z, alpha*f3.x+bb0.w);
        float4 vlo1 = make_float4(alpha*f4.x+bb1.x, alpha*f5.x+bb1.y, alpha*f6.x+bb1.z, alpha*f7.x+bb1.w);
        float4 vhi0 = make_float4(alpha*f0.y+bb0.x, alpha*f1.y+bb0.y, alpha*f2.y+bb0.z, alpha*f3.y+bb0.w);
        float4 vhi1 = make_float4(alpha*f4.y+bb1.x, alpha*f5.y+bb1.y, alpha*f6.y+bb1.z, alpha*f7.y+bb1.w);
        *(float4*)&C[base0]      = vlo0;
        *(float4*)&C[base0 + 64] = vlo1;
        *(float4*)&C[base1]      = vhi0;
        *(float4*)&C[base1 + 64] = vhi1;
    }
}

// ---------------- kernels ----------------

__global__ void k_init(const float* __restrict__ hid){
    int i = blockIdx.x*blockDim.x + threadIdx.x;   // 0 .. 2*BH-1
    if (i < BH) g_prev0[i] = hid[i];
    else        g_prev1[i - BH] = hid[i];
}

// Xin[m,:] = sqrt(E) * emb[tok[m],:] @ W_in^T    grid (32 mtiles, 8 ntiles)
__global__ void __launch_bounds__(256,2) k_xin(const int* __restrict__ toks,
                                               const float* __restrict__ emb,
                                               const float* __restrict__ Win){
    gemm_core<128,256>(emb, EMBD, blockIdx.x*128, toks,
                       Win, EMBD, blockIdx.y*128,
                       0, EMBD,
                       g_Xin, HID, blockIdx.x*128, blockIdx.y*128,
                       SQRTE, nullptr);
}

// layer-0 reset/forget U-GEMM partials.  grid (8 ntile, 2 gate, 8 ksplit)
__global__ void __launch_bounds__(128,2) k_gates0(const float* __restrict__ Ur0,
                                                  const float* __restrict__ Uf0){
    const float* Wm = blockIdx.y ? Uf0 : Ur0;
    float* C = g_part + (size_t)(blockIdx.y*8 + blockIdx.z)*BH;
    gemm_core<64,128>(g_prev0, HID, 0, nullptr, Wm, HID, blockIdx.x*128,
                      blockIdx.z*128, 128, C, HID, 0, blockIdx.x*128, 1.f, nullptr);
}

__global__ void k_fin0(int t, const float* __restrict__ br0, const float* __restrict__ bf0){
    int i = blockIdx.x*blockDim.x + threadIdx.x;   // 0..BH-1
    int n = i & (HID-1);
    float s0 = 0.f, s1 = 0.f;
#pragma unroll
    for (int ks = 0; ks < 8; ks++){
        s0 += g_part[(size_t)ks*BH + i];
        s1 += g_part[(size_t)(8+ks)*BH + i];
    }
    float xv = g_Xin[(size_t)t*BH + i];
    float rpre = xv + br0[n] + s0;
    float fpre = xv + bf0[n] + s1;
    g_r0pre[i] = rpre;
    g_f0pre[i] = fpre;
    g_rp0[i] = sigmf(rpre) * g_prev0[i];
    g_z0[i]  = sigmf(fpre);
}

// job0: (r0*prev0)@Uh0^T            (K=1024 in 16 splits of 64)
// job1: reset0@Wr1^T + prev1@Ur1^T  (fused K=2048, 16 splits of 128)
// job2: forget0@Wf1^T + prev1@Uf1^T (fused K=2048, 16 splits of 128)
// grid (8 ntile, 3 job, 16 ksplit)
__global__ void __launch_bounds__(128,2) k_mid(const float* __restrict__ Uh0,
                                               const float* __restrict__ Wr1,
                                               const float* __restrict__ Ur1,
                                               const float* __restrict__ Wf1,
                                               const float* __restrict__ Uf1){
    int nt = blockIdx.x, job = blockIdx.y, ks = blockIdx.z;
    const float *Ap, *Wp; int k0, kLen;
    if (job == 0){ Ap = g_rp0; Wp = Uh0; k0 = ks*64; kLen = 64; }
    else {
        const float* pre = (job == 1) ? g_r0pre : g_f0pre;
        const float* Wx  = (job == 1) ? Wr1 : Wf1;
        const float* Ux  = (job == 1) ? Ur1 : Uf1;
        if (ks < 8){ Ap = pre;     Wp = Wx; k0 = ks*128; }
        else       { Ap = g_prev1; Wp = Ux; k0 = (ks-8)*128; }
        kLen = 128;
    }
    float* C = g_part + (size_t)(job*16 + ks)*BH;
    gemm_core<64,128>(Ap, HID, 0, nullptr, Wp, HID, nt*128, k0, kLen,
                      C, HID, 0, nt*128, 1.f, nullptr);
}

__global__ void k_fin_mid(int t, const float* __restrict__ bh0,
                          const float* __restrict__ br1, const float* __restrict__ bf1){
    int i = blockIdx.x*blockDim.x + threadIdx.x;
    int n = i & (HID-1);
    float s0 = 0.f, s1 = 0.f, s2 = 0.f;
#pragma unroll
    for (int ks = 0; ks < 16; ks++){
        s0 += g_part[(size_t)ks*BH + i];
        s1 += g_part[(size_t)(16+ks)*BH + i];
        s2 += g_part[(size_t)(32+ks)*BH + i];
    }
    float htil0 = g_Xin[(size_t)t*BH + i] + bh0[n] + s0;
    float z  = g_z0[i];
    float p0 = g_prev0[i];
    g_prev0[i] = (1.0f - z)*p0 + z*tanhf(htil0);   // h0 (new layer-0 state)
    g_h0pre[i] = htil0;                             // layer-1 candidate input
    float r1p = s1 + br1[n];
    float f1p = s2 + bf1[n];
    float p1 = g_prev1[i];
    g_rp1[i] = sigmf(r1p) * p1;
    g_z1[i]  = sigmf(f1p);
}

// htil0@Wh1^T + (r1*prev1)@Uh1^T (fused K=2048).  grid (8 ntile, 16 ksplit)
__global__ void __launch_bounds__(128,2) k_last(const float* __restrict__ Wh1,
                                                const float* __restrict__ Uh1){
    int nt = blockIdx.x, ks = blockIdx.y;
    const float *Ap, *Wp; int k0;
    if (ks < 8){ Ap = g_h0pre; Wp = Wh1; k0 = ks*128; }
    else       { Ap = g_rp1;   Wp = Uh1; k0 = (ks-8)*128; }
    float* C = g_part + (size_t)ks*BH;
    gemm_core<64,128>(Ap, HID, 0, nullptr, Wp, HID, nt*128, k0, 128,
                      C, HID, 0, nt*128, 1.f, nullptr);
}

__global__ void k_fin_last(int t, const float* __restrict__ bh1){
    int i = blockIdx.x*blockDim.x + threadIdx.x;
    int n = i & (HID-1);
    float s = 0.f;
#pragma unroll
    for (int ks = 0; ks < 16; ks++) s += g_part[(size_t)ks*BH + i];
    float htil1 = s + bh1[n];
    float z  = g_z1[i];
    float p1 = g_prev1[i];
    float h  = (1.0f - z)*p1 + z*tanhf(htil1);
    g_prev1[i] = h;
    g_H[(size_t)t*BH + i] = h;
}

// logits = g_H @ out_W^T + out_b    grid (32 mtiles, 250 ntiles)
__global__ void __launch_bounds__(256,2) k_out(const float* __restrict__ outW,
                                               const float* __restrict__ outb,
                                               float* __restrict__ logits){
    gemm_core<128,256>(g_H, HID, blockIdx.x*128, nullptr,
                       outW, HID, blockIdx.y*128,
                       0, HID,
                       logits, VOCAB, blockIdx.x*128, blockIdx.y*128,
                       1.0f, outb);
}

__global__ void k_copy(float* __restrict__ dst){
    int i = blockIdx.x*blockDim.x + threadIdx.x;   // 0 .. 2*BH-1
    dst[i] = (i < BH) ? g_prev0[i] : g_prev1[i - BH];
}

// ---------------- launch ----------------
extern "C" void kernel_launch(void* const* d_in, const int* in_sizes, int n_in,
                              void* d_out, int out_size) {
    const int*   toks = (const int*)  d_in[0];
    const float* hid  = (const float*)d_in[1];
    const float* emb  = (const float*)d_in[2];
    const float* Win  = (const float*)d_in[3];
    const float* Wr1  = (const float*)d_in[4];
    const float* Wf1  = (const float*)d_in[5];
    const float* Wh1  = (const float*)d_in[6];
    const float* Ur   = (const float*)d_in[7];
    const float* br   = (const float*)d_in[8];
    const float* Uf   = (const float*)d_in[9];
    const float* bf   = (const float*)d_in[10];
    const float* Uh   = (const float*)d_in[11];
    const float* bh   = (const float*)d_in[12];
    const float* outW = (const float*)d_in[13];
    const float* outb = (const float*)d_in[14];
    float* out = (float*)d_out;

    const float *Ur0 = Ur,        *Ur1 = Ur + HID*HID;
    const float *Uf0 = Uf,        *Uf1 = Uf + HID*HID;
    const float *Uh0 = Uh,        *Uh1 = Uh + HID*HID;
    const float *br0 = br, *br1 = br + HID;
    const float *bf0 = bf, *bf1 = bf + HID;
    const float *bh0 = bh, *bh1 = bh + HID;

    k_init<<<2*BH/256, 256>>>(hid);
    k_xin<<<dim3(32,8), 256>>>(toks, emb, Win);

    for (int t = 0; t < SEQL; t++){
        k_gates0 <<<dim3(8,2,8),  128>>>(Ur0, Uf0);
        k_fin0   <<<BH/256,       256>>>(t, br0, bf0);
        k_mid    <<<dim3(8,3,16), 128>>>(Uh0, Wr1, Ur1, Wf1, Uf1);
        k_fin_mid<<<BH/256,       256>>>(t, bh0, br1, bf1);
        k_last   <<<dim3(8,16),   128>>>(Wh1, Uh1);
        k_fin_last<<<BH/256,      256>>>(t, bh1);
    }

    k_out<<<dim3(32,250), 256>>>(outW, outb, out);

    if ((size_t)out_size >= LOGITS_N + 2*(size_t)BH)
        k_copy<<<2*BH/256, 256>>>(out + LOGITS_N);
}

// round 6
// speedup vs baseline: 1.4524x; 1.4524x over previous
#include <cuda_runtime.h>
#include <cuda_bf16.h>
#include <math.h>
#include <stdint.h>

// ---------------- problem constants ----------------
#define SEQL  64
#define BATCH 64
#define HID   1024
#define EMBD  1024
#define VOCAB 32000
#define BH    (BATCH*HID)            // 65536
#define LOGITS_N ((size_t)SEQL*BATCH*VOCAB)
#define SQRTE 32.0f                  // sqrt(1024)

typedef unsigned long long u64;

// ---------------- packed f32x2 helpers ----------------
__device__ __forceinline__ u64 pk2(float lo, float hi){
    u64 r; asm("mov.b64 %0, {%1, %2};" : "=l"(r) : "f"(lo), "f"(hi)); return r;
}
__device__ __forceinline__ void fma2(u64 &d, u64 a, u64 b){
    asm("fma.rn.f32x2 %0, %1, %2, %0;" : "+l"(d) : "l"(a), "l"(b));
}
__device__ __forceinline__ float2 unpk2(u64 v){
    float2 f; asm("mov.b64 {%0, %1}, %2;" : "=f"(f.x), "=f"(f.y) : "l"(v)); return f;
}
__device__ __forceinline__ float sigmf(float x){ return 1.0f/(1.0f + expf(-x)); }

// ---------------- smem / async-copy / mma helpers (portable PTX) ----------------
__device__ __forceinline__ uint32_t smem_u32(const void* p){
    uint32_t a;
    asm("{ .reg .u64 t; cvta.to.shared.u64 t, %1; cvt.u32.u64 %0, t; }" : "=r"(a) : "l"(p));
    return a;
}
#define CP16(sa, gp) \
    asm volatile("cp.async.cg.shared.global [%0], [%1], 16;" :: "r"((uint32_t)(sa)), "l"(gp) : "memory")
#define CP_COMMIT() asm volatile("cp.async.commit_group;" ::: "memory")
#define CP_WAIT(n)  asm volatile("cp.async.wait_group %0;" :: "n"(n) : "memory")

__device__ __forceinline__ void ldsm4(uint32_t* r, uint32_t addr){
    asm volatile("ldmatrix.sync.aligned.m8n8.x4.shared.b16 {%0,%1,%2,%3}, [%4];"
        : "=r"(r[0]), "=r"(r[1]), "=r"(r[2]), "=r"(r[3]) : "r"(addr));
}
__device__ __forceinline__ void mma_bf16(float* d, const uint32_t* a, const uint32_t* b){
    asm volatile(
        "mma.sync.aligned.m16n8k16.row.col.f32.bf16.bf16.f32 "
        "{%0,%1,%2,%3}, {%4,%5,%6,%7}, {%8,%9}, {%0,%1,%2,%3};"
        : "+f"(d[0]), "+f"(d[1]), "+f"(d[2]), "+f"(d[3])
        : "r"(a[0]), "r"(a[1]), "r"(a[2]), "r"(a[3]), "r"(b[0]), "r"(b[1]));
}

// ---------------- device scratch ----------------
__device__ __align__(16) float g_Xin[SEQL*BH];
__device__ __align__(16) float g_prev0[BH];
__device__ __align__(16) float g_prev1[BH];
__device__ __align__(16) float g_r0pre[BH];
__device__ __align__(16) float g_f0pre[BH];
__device__ __align__(16) float g_h0pre[BH];
__device__ __align__(16) float g_rp0[BH];
__device__ __align__(16) float g_z0[BH];
__device__ __align__(16) float g_rp1[BH];
__device__ __align__(16) float g_z1[BH];
__device__ __align__(16) float g_part[48*BH];
// split-bf16 operands for tensor-core output GEMM
__device__ __align__(16) __nv_bfloat16 gH_hi[SEQL*BH];
__device__ __align__(16) __nv_bfloat16 gH_lo[SEQL*BH];
__device__ __align__(16) __nv_bfloat16 gW_hi[(size_t)VOCAB*HID];
__device__ __align__(16) __nv_bfloat16 gW_lo[(size_t)VOCAB*HID];

// ---------------- fp32 C = alpha*(A · Wᵀ) tile core (recurrence path) ----------------
template<int BM, int NTH>
__device__ __forceinline__ void gemm_core(
    const float* __restrict__ A, int lda, int aRow0, const int* __restrict__ aMap,
    const float* __restrict__ W, int ldw, int wRow0,
    int k0, int kLen,
    float* __restrict__ C, int ldc, int cRow0, int cCol0,
    float alpha, const float* __restrict__ bias)
{
    constexpr int BN  = 128;
    constexpr int BKt = 16;
    constexpr int AF4   = (BM*BKt)/(4*NTH);
    constexpr int WF4   = (BN*BKt)/(4*NTH);
    constexpr int RSTEP = NTH/4;

    __shared__ __align__(16) float sA[BKt][BM];
    __shared__ __align__(16) float sW[BKt][BN];

    const int tid = threadIdx.x;
    const int lr  = tid >> 2;
    const int kq  = tid & 3;
    const int tx  = tid & 15;
    const int ty  = tid >> 4;

    const float* aPtr[AF4];
#pragma unroll
    for (int i = 0; i < AF4; i++){
        int r  = aRow0 + lr + i*RSTEP;
        int rr = aMap ? aMap[r] : r;
        aPtr[i] = A + (size_t)rr*lda + (k0 + kq*4);
    }
    const float* wPtr[WF4];
#pragma unroll
    for (int i = 0; i < WF4; i++)
        wPtr[i] = W + (size_t)(wRow0 + lr + i*RSTEP)*ldw + (k0 + kq*4);

    u64 acc[4][8];
#pragma unroll
    for (int p = 0; p < 4; p++)
#pragma unroll
        for (int n = 0; n < 8; n++) acc[p][n] = 0ull;

    for (int k = 0; k < kLen; k += BKt){
        float4 av[AF4], wv[WF4];
#pragma unroll
        for (int i = 0; i < AF4; i++) av[i] = *(const float4*)(aPtr[i] + k);
#pragma unroll
        for (int i = 0; i < WF4; i++) wv[i] = *(const float4*)(wPtr[i] + k);
        __syncthreads();
#pragma unroll
        for (int i = 0; i < AF4; i++){
            int r = lr + i*RSTEP;
            sA[kq*4+0][r] = av[i].x; sA[kq*4+1][r] = av[i].y;
            sA[kq*4+2][r] = av[i].z; sA[kq*4+3][r] = av[i].w;
        }
#pragma unroll
        for (int i = 0; i < WF4; i++){
            int r = lr + i*RSTEP;
            sW[kq*4+0][r] = wv[i].x; sW[kq*4+1][r] = wv[i].y;
            sW[kq*4+2][r] = wv[i].z; sW[kq*4+3][r] = wv[i].w;
        }
        __syncthreads();
#pragma unroll
        for (int kk = 0; kk < BKt; kk++){
            float4 aL = *(const float4*)&sA[kk][ty*4];
            float4 aH = *(const float4*)&sA[kk][BM/2 + ty*4];
            u64 ap[4] = { pk2(aL.x,aL.y), pk2(aL.z,aL.w),
                          pk2(aH.x,aH.y), pk2(aH.z,aH.w) };
            float4 b0 = *(const float4*)&sW[kk][tx*4];
            float4 b1 = *(const float4*)&sW[kk][64 + tx*4];
            float bv[8] = {b0.x,b0.y,b0.z,b0.w,b1.x,b1.y,b1.z,b1.w};
#pragma unroll
            for (int n = 0; n < 8; n++){
                u64 bd = pk2(bv[n], bv[n]);
#pragma unroll
                for (int p = 0; p < 4; p++) fma2(acc[p][n], ap[p], bd);
            }
        }
    }

    float4 bb0 = make_float4(0.f,0.f,0.f,0.f), bb1 = bb0;
    if (bias){
        bb0 = *(const float4*)&bias[cCol0 + tx*4];
        bb1 = *(const float4*)&bias[cCol0 + 64 + tx*4];
    }
#pragma unroll
    for (int p = 0; p < 4; p++){
        float2 f0 = unpk2(acc[p][0]), f1 = unpk2(acc[p][1]);
        float2 f2 = unpk2(acc[p][2]), f3 = unpk2(acc[p][3]);
        float2 f4 = unpk2(acc[p][4]), f5 = unpk2(acc[p][5]);
        float2 f6 = unpk2(acc[p][6]), f7 = unpk2(acc[p][7]);
        int rloc = ((p < 2) ? 0 : BM/2) + ty*4 + (p & 1)*2;
        size_t base0 = (size_t)(cRow0 + rloc    )*ldc + cCol0 + tx*4;
        size_t base1 = (size_t)(cRow0 + rloc + 1)*ldc + cCol0 + tx*4;
        float4 vlo0 = make_float4(alpha*f0.x+bb0.x, alpha*f1.x+bb0.y, alpha*f2.x+bb0.z, alpha*f3.x+bb0.w);
        float4 vlo1 = make_float4(alpha*f4.x+bb1.x, alpha*f5.x+bb1.y, alpha*f6.x+bb1.z, alpha*f7.x+bb1.w);
        float4 vhi0 = make_float4(alpha*f0.y+bb0.x, alpha*f1.y+bb0.y, alpha*f2.y+bb0.z, alpha*f3.y+bb0.w);
        float4 vhi1 = make_float4(alpha*f4.y+bb1.x, alpha*f5.y+bb1.y, alpha*f6.y+bb1.z, alpha*f7.y+bb1.w);
        *(float4*)&C[base0]      = vlo0;
        *(float4*)&C[base0 + 64] = vlo1;
        *(float4*)&C[base1]      = vhi0;
        *(float4*)&C[base1 + 64] = vhi1;
    }
}

// ---------------- small kernels ----------------
__global__ void k_init(const float* __restrict__ hid){
    int i = blockIdx.x*blockDim.x + threadIdx.x;
    if (i < BH) g_prev0[i] = hid[i];
    else        g_prev1[i - BH] = hid[i];
}

// split out_W into bf16 hi/lo
__global__ void k_cvtW(const float* __restrict__ W){
    size_t i4 = (size_t)blockIdx.x*blockDim.x + threadIdx.x;
    float4 v = *(const float4*)(W + i4*4);
    __nv_bfloat162 hA = __floats2bfloat162_rn(v.x, v.y);
    __nv_bfloat162 hB = __floats2bfloat162_rn(v.z, v.w);
    __nv_bfloat162 lA = __floats2bfloat162_rn(v.x - __low2float(hA), v.y - __high2float(hA));
    __nv_bfloat162 lB = __floats2bfloat162_rn(v.z - __low2float(hB), v.w - __high2float(hB));
    *(__nv_bfloat162*)(gW_hi + i4*4)     = hA;
    *(__nv_bfloat162*)(gW_hi + i4*4 + 2) = hB;
    *(__nv_bfloat162*)(gW_lo + i4*4)     = lA;
    *(__nv_bfloat162*)(gW_lo + i4*4 + 2) = lB;
}

// Xin[m,:] = sqrt(E) * emb[tok[m],:] @ W_in^T
__global__ void __launch_bounds__(256,2) k_xin(const int* __restrict__ toks,
                                               const float* __restrict__ emb,
                                               const float* __restrict__ Win){
    gemm_core<128,256>(emb, EMBD, blockIdx.x*128, toks,
                       Win, EMBD, blockIdx.y*128,
                       0, EMBD,
                       g_Xin, HID, blockIdx.x*128, blockIdx.y*128,
                       SQRTE, nullptr);
}

// layer-0 reset/forget U-GEMMs.  grid (8 ntile, 2 gate, 8 ksplit)
__global__ void __launch_bounds__(128,2) k_gates0(const float* __restrict__ Ur0,
                                                  const float* __restrict__ Uf0){
    const float* Wm = blockIdx.y ? Uf0 : Ur0;
    float* C = g_part + (size_t)(blockIdx.y*8 + blockIdx.z)*BH;
    gemm_core<64,128>(g_prev0, HID, 0, nullptr, Wm, HID, blockIdx.x*128,
                      blockIdx.z*128, 128, C, HID, 0, blockIdx.x*128, 1.f, nullptr);
}

__global__ void k_fin0(int t, const float* __restrict__ br0, const float* __restrict__ bf0){
    int i = blockIdx.x*blockDim.x + threadIdx.x;
    int n = i & (HID-1);
    float s0 = 0.f, s1 = 0.f;
#pragma unroll
    for (int ks = 0; ks < 8; ks++){
        s0 += g_part[(size_t)ks*BH + i];
        s1 += g_part[(size_t)(8+ks)*BH + i];
    }
    float xv = g_Xin[(size_t)t*BH + i];
    float rpre = xv + br0[n] + s0;
    float fpre = xv + bf0[n] + s1;
    g_r0pre[i] = rpre;
    g_f0pre[i] = fpre;
    g_rp0[i] = sigmf(rpre) * g_prev0[i];
    g_z0[i]  = sigmf(fpre);
}

// job0: (r0*prev0)@Uh0^T (K=1024, 8x128); job1/2: fused K=2048, 8 splits of 256
__global__ void __launch_bounds__(128,2) k_mid(const float* __restrict__ Uh0,
                                               const float* __restrict__ Wr1,
                                               const float* __restrict__ Ur1,
                                               const float* __restrict__ Wf1,
                                               const float* __restrict__ Uf1){
    int nt = blockIdx.x, job = blockIdx.y, ks = blockIdx.z;
    const float *Ap, *Wp; int k0, kLen;
    if (job == 0){ Ap = g_rp0; Wp = Uh0; k0 = ks*128; kLen = 128; }
    else {
        const float* pre = (job == 1) ? g_r0pre : g_f0pre;
        const float* Wx  = (job == 1) ? Wr1 : Wf1;
        const float* Ux  = (job == 1) ? Ur1 : Uf1;
        if (ks < 4){ Ap = pre;     Wp = Wx; k0 = ks*256; }
        else       { Ap = g_prev1; Wp = Ux; k0 = (ks-4)*256; }
        kLen = 256;
    }
    float* C = g_part + (size_t)(job*8 + ks)*BH;
    gemm_core<64,128>(Ap, HID, 0, nullptr, Wp, HID, nt*128, k0, kLen,
                      C, HID, 0, nt*128, 1.f, nullptr);
}

__global__ void k_fin_mid(int t, const float* __restrict__ bh0,
                          const float* __restrict__ br1, const float* __restrict__ bf1){
    int i = blockIdx.x*blockDim.x + threadIdx.x;
    int n = i & (HID-1);
    float s0 = 0.f, s1 = 0.f, s2 = 0.f;
#pragma unroll
    for (int ks = 0; ks < 8; ks++){
        s0 += g_part[(size_t)ks*BH + i];
        s1 += g_part[(size_t)(8+ks)*BH + i];
        s2 += g_part[(size_t)(16+ks)*BH + i];
    }
    float htil0 = g_Xin[(size_t)t*BH + i] + bh0[n] + s0;
    float z  = g_z0[i];
    float p0 = g_prev0[i];
    g_prev0[i] = (1.0f - z)*p0 + z*tanhf(htil0);
    g_h0pre[i] = htil0;
    float r1p = s1 + br1[n];
    float f1p = s2 + bf1[n];
    float p1 = g_prev1[i];
    g_rp1[i] = sigmf(r1p) * p1;
    g_z1[i]  = sigmf(f1p);
}

// htil0@Wh1^T + (r1*prev1)@Uh1^T (fused K=2048).  grid (8 ntile, 16 ksplit)
__global__ void __launch_bounds__(128,2) k_last(const float* __restrict__ Wh1,
                                                const float* __restrict__ Uh1){
    int nt = blockIdx.x, ks = blockIdx.y;
    const float *Ap, *Wp; int k0;
    if (ks < 8){ Ap = g_h0pre; Wp = Wh1; k0 = ks*128; }
    else       { Ap = g_rp1;   Wp = Uh1; k0 = (ks-8)*128; }
    float* C = g_part + (size_t)ks*BH;
    gemm_core<64,128>(Ap, HID, 0, nullptr, Wp, HID, nt*128, k0, 128,
                      C, HID, 0, nt*128, 1.f, nullptr);
}

__global__ void k_fin_last(int t, const float* __restrict__ bh1){
    int i = blockIdx.x*blockDim.x + threadIdx.x;
    int n = i & (HID-1);
    float s = 0.f;
#pragma unroll
    for (int ks = 0; ks < 16; ks++) s += g_part[(size_t)ks*BH + i];
    float htil1 = s + bh1[n];
    float z  = g_z1[i];
    float p1 = g_prev1[i];
    float h  = (1.0f - z)*p1 + z*tanhf(htil1);
    g_prev1[i] = h;
    __nv_bfloat16 hh = __float2bfloat16_rn(h);
    gH_hi[(size_t)t*BH + i] = hh;
    gH_lo[(size_t)t*BH + i] = __float2bfloat16_rn(h - __bfloat162float(hh));
}

// ---------------- mma.sync output GEMM ----------------
// logits[4096 x 32000] = H @ outW^T + outb, split-bf16, fp32 acc.
// CTA tile 128x128, BK=32, 8 warps (warp 64x32), 2-stage cp.async pipeline.
// smem pitch 80B (64B data + 16B pad) -> conflict-free LDSM (i*20 mod 32 distinct).
#define OSTAGE 40960                 // Ahi 10240 | Alo 10240 | Bhi 10240 | Blo 10240
#define OSMEM  (2*OSTAGE)            // 81920
#define OKIT   (HID/32)              // 32 k-iterations

__global__ void __launch_bounds__(256,1) k_out_mma(const float* __restrict__ outb,
                                                   float* __restrict__ logits){
    extern __shared__ __align__(128) char smem[];
    const uint32_t sb = smem_u32(smem);
    const int tid  = threadIdx.x;
    const int lane = tid & 31;
    const int wid  = tid >> 5;
    const int wm   = wid >> 2;          // 0..1
    const int wn   = wid & 3;           // 0..3
    const int m0 = blockIdx.x * 128;
    const int n0 = blockIdx.y * 128;

    // ---- global->smem mapping: 8 x 16B cp.async per thread per stage ----
    const int rowg = tid >> 2;          // 0..63
    const int seg  = tid & 3;
    const uint32_t soff = (uint32_t)rowg*80 + seg*16;
    const __nv_bfloat16* pAh = gH_hi + (size_t)(m0 + rowg)*HID + seg*8;
    const __nv_bfloat16* pAl = gH_lo + (size_t)(m0 + rowg)*HID + seg*8;
    const __nv_bfloat16* pBh = gW_hi + (size_t)(n0 + rowg)*HID + seg*8;
    const __nv_bfloat16* pBl = gW_lo + (size_t)(n0 + rowg)*HID + seg*8;
    const size_t rstep = (size_t)64*HID;

    auto issue = [&](int buf, int k0){
        uint32_t s0 = sb + buf*OSTAGE;
        CP16(s0 +         soff,         pAh + k0);
        CP16(s0 +         soff + 64*80, pAh + k0 + rstep);
        CP16(s0 + 10240 + soff,         pAl + k0);
        CP16(s0 + 10240 + soff + 64*80, pAl + k0 + rstep);
        CP16(s0 + 20480 + soff,         pBh + k0);
        CP16(s0 + 20480 + soff + 64*80, pBh + k0 + rstep);
        CP16(s0 + 30720 + soff,         pBl + k0);
        CP16(s0 + 30720 + soff + 64*80, pBl + k0 + rstep);
    };

    // ---- ldmatrix per-lane address bases ----
    const int rowA = (lane & 7) + ((lane >> 3) & 1)*8;
    const uint32_t aoff = (uint32_t)(wm*64 + rowA)*80 + (uint32_t)(lane >> 4)*16;
    const int rowB = (lane & 7) + (lane >> 4)*8;
    const uint32_t boff = 20480u + (uint32_t)(wn*32 + rowB)*80 + (uint32_t)((lane >> 3) & 1)*16;

    float acc[4][4][4];
#pragma unroll
    for (int mi = 0; mi < 4; mi++)
#pragma unroll
        for (int ni = 0; ni < 4; ni++)
#pragma unroll
            for (int r = 0; r < 4; r++) acc[mi][ni][r] = 0.f;

    issue(0, 0);
    CP_COMMIT();

    for (int s = 0; s < OKIT; s++){
        if (s + 1 < OKIT){ issue((s+1)&1, (s+1)*32); CP_COMMIT(); }
        if (s + 1 < OKIT) CP_WAIT(1); else CP_WAIT(0);
        __syncthreads();

        const uint32_t st = sb + (s&1)*OSTAGE;
#pragma unroll
        for (int kk = 0; kk < 2; kk++){
            uint32_t aH[4][4], aL[4][4], bH[4][2], bL[4][2];
#pragma unroll
            for (int mi = 0; mi < 4; mi++){
                ldsm4(aH[mi], st +         aoff + mi*(16*80) + kk*32);
                ldsm4(aL[mi], st + 10240 + aoff + mi*(16*80) + kk*32);
            }
#pragma unroll
            for (int p = 0; p < 2; p++){
                uint32_t t[4];
                ldsm4(t, st +         boff + p*(16*80) + kk*32);
                bH[2*p][0]=t[0]; bH[2*p][1]=t[1]; bH[2*p+1][0]=t[2]; bH[2*p+1][1]=t[3];
                ldsm4(t, st + 10240 + boff + p*(16*80) + kk*32);
                bL[2*p][0]=t[0]; bL[2*p][1]=t[1]; bL[2*p+1][0]=t[2]; bL[2*p+1][1]=t[3];
            }
#pragma unroll
            for (int mi = 0; mi < 4; mi++)
#pragma unroll
                for (int ni = 0; ni < 4; ni++){
                    mma_bf16(acc[mi][ni], aH[mi], bH[ni]);
                    mma_bf16(acc[mi][ni], aH[mi], bL[ni]);
                    mma_bf16(acc[mi][ni], aL[mi], bH[ni]);
                }
        }
        __syncthreads();
    }

    // ---- epilogue: +bias, direct STG (float2 per fragment half) ----
    const int mBase = m0 + wm*64 + (lane >> 2);
    const int nBase = n0 + wn*32 + (lane & 3)*2;
    float2 bv[4];
#pragma unroll
    for (int ni = 0; ni < 4; ni++) bv[ni] = *(const float2*)&outb[nBase + ni*8];
#pragma unroll
    for (int mi = 0; mi < 4; mi++)
#pragma unroll
        for (int ni = 0; ni < 4; ni++){
#pragma unroll
            for (int r = 0; r < 2; r++){
                int m = mBase + mi*16 + r*8;
                float2 v = make_float2(acc[mi][ni][2*r] + bv[ni].x,
                                       acc[mi][ni][2*r+1] + bv[ni].y);
                *(float2*)&logits[(size_t)m*VOCAB + nBase + ni*8] = v;
            }
        }
}

__global__ void k_copy(float* __restrict__ dst){
    int i = blockIdx.x*blockDim.x + threadIdx.x;
    dst[i] = (i < BH) ? g_prev0[i] : g_prev1[i - BH];
}

// ---------------- launch ----------------
extern "C" void kernel_launch(void* const* d_in, const int* in_sizes, int n_in,
                              void* d_out, int out_size) {
    const int*   toks = (const int*)  d_in[0];
    const float* hid  = (const float*)d_in[1];
    const float* emb  = (const float*)d_in[2];
    const float* Win  = (const float*)d_in[3];
    const float* Wr1  = (const float*)d_in[4];
    const float* Wf1  = (const float*)d_in[5];
    const float* Wh1  = (const float*)d_in[6];
    const float* Ur   = (const float*)d_in[7];
    const float* br   = (const float*)d_in[8];
    const float* Uf   = (const float*)d_in[9];
    const float* bf   = (const float*)d_in[10];
    const float* Uh   = (const float*)d_in[11];
    const float* bh   = (const float*)d_in[12];
    const float* outW = (const float*)d_in[13];
    const float* outb = (const float*)d_in[14];
    float* out = (float*)d_out;

    const float *Ur0 = Ur, *Ur1 = Ur + HID*HID;
    const float *Uf0 = Uf, *Uf1 = Uf + HID*HID;
    const float *Uh0 = Uh, *Uh1 = Uh + HID*HID;
    const float *br0 = br, *br1 = br + HID;
    const float *bf0 = bf, *bf1 = bf + HID;
    const float *bh0 = bh, *bh1 = bh + HID;

    cudaFuncSetAttribute(k_out_mma, cudaFuncAttributeMaxDynamicSharedMemorySize, OSMEM);

    k_init<<<2*BH/256, 256>>>(hid);
    k_cvtW<<<(VOCAB*HID/4)/256, 256>>>(outW);
    k_xin<<<dim3(32,8), 256>>>(toks, emb, Win);

    for (int t = 0; t < SEQL; t++){
        k_gates0  <<<dim3(8,2,8), 128>>>(Ur0, Uf0);
        k_fin0    <<<BH/256,      256>>>(t, br0, bf0);
        k_mid     <<<dim3(8,3,8), 128>>>(Uh0, Wr1, Ur1, Wf1, Uf1);
        k_fin_mid <<<BH/256,      256>>>(t, bh0, br1, bf1);
        k_last    <<<dim3(8,16),  128>>>(Wh1, Uh1);
        k_fin_last<<<BH/256,      256>>>(t, bh1);
    }

    k_out_mma<<<dim3(32,250), 256, OSMEM>>>(outb, out);

    if ((size_t)out_size >= LOGITS_N + 2*(size_t)BH)
        k_copy<<<2*BH/256, 256>>>(out + LOGITS_N);
}

// round 7
// speedup vs baseline: 1.9912x; 1.3710x over previous
#include <cuda_runtime.h>
#include <cuda_bf16.h>
#include <math.h>
#include <stdint.h>

// ---------------- problem constants ----------------
#define SEQL  64
#define BATCH 64
#define HID   1024
#define EMBD  1024
#define VOCAB 32000
#define BH    (BATCH*HID)            // 65536
#define LOGITS_N ((size_t)SEQL*BATCH*VOCAB)
#define SQRTE 32.0f                  // sqrt(1024)
#define HH    (HID*HID)

typedef unsigned long long u64;

// ---------------- packed f32x2 helpers (fp32 path for k_xin) ----------------
__device__ __forceinline__ u64 pk2(float lo, float hi){
    u64 r; asm("mov.b64 %0, {%1, %2};" : "=l"(r) : "f"(lo), "f"(hi)); return r;
}
__device__ __forceinline__ void fma2(u64 &d, u64 a, u64 b){
    asm("fma.rn.f32x2 %0, %1, %2, %0;" : "+l"(d) : "l"(a), "l"(b));
}
__device__ __forceinline__ float2 unpk2(u64 v){
    float2 f; asm("mov.b64 {%0, %1}, %2;" : "=f"(f.x), "=f"(f.y) : "l"(v)); return f;
}
__device__ __forceinline__ float sigmf(float x){ return 1.0f/(1.0f + expf(-x)); }

// ---------------- smem / async-copy / mma helpers (portable PTX) ----------------
__device__ __forceinline__ uint32_t smem_u32(const void* p){
    uint32_t a;
    asm("{ .reg .u64 t; cvta.to.shared.u64 t, %1; cvt.u32.u64 %0, t; }" : "=r"(a) : "l"(p));
    return a;
}
#define CP16(sa, gp) \
    asm volatile("cp.async.cg.shared.global [%0], [%1], 16;" :: "r"((uint32_t)(sa)), "l"(gp) : "memory")
#define CP_COMMIT() asm volatile("cp.async.commit_group;" ::: "memory")
#define CP_WAIT(n)  asm volatile("cp.async.wait_group %0;" :: "n"(n) : "memory")

__device__ __forceinline__ void ldsm4(uint32_t* r, uint32_t addr){
    asm volatile("ldmatrix.sync.aligned.m8n8.x4.shared.b16 {%0,%1,%2,%3}, [%4];"
        : "=r"(r[0]), "=r"(r[1]), "=r"(r[2]), "=r"(r[3]) : "r"(addr));
}
__device__ __forceinline__ void mma_bf16(float* d, const uint32_t* a, const uint32_t* b){
    asm volatile(
        "mma.sync.aligned.m16n8k16.row.col.f32.bf16.bf16.f32 "
        "{%0,%1,%2,%3}, {%4,%5,%6,%7}, {%8,%9}, {%0,%1,%2,%3};"
        : "+f"(d[0]), "+f"(d[1]), "+f"(d[2]), "+f"(d[3])
        : "r"(a[0]), "r"(a[1]), "r"(a[2]), "r"(a[3]), "r"(b[0]), "r"(b[1]));
}

// ---------------- device scratch ----------------
__device__ __align__(16) float g_Xin[SEQL*BH];
__device__ __align__(16) float g_prev0[BH];
__device__ __align__(16) float g_prev1[BH];
__device__ __align__(16) float g_z0[BH];
__device__ __align__(16) float g_z1[BH];
__device__ __align__(16) float g_part[24*BH];
// bf16 hi/lo activation operands for the recurrence HMMA GEMMs
__device__ __align__(16) __nv_bfloat16 b_prev0_h[BH], b_prev0_l[BH];
__device__ __align__(16) __nv_bfloat16 b_prev1_h[BH], b_prev1_l[BH];
__device__ __align__(16) __nv_bfloat16 b_rp0_h[BH],   b_rp0_l[BH];
__device__ __align__(16) __nv_bfloat16 b_rp1_h[BH],   b_rp1_l[BH];
__device__ __align__(16) __nv_bfloat16 b_r0pre_h[BH], b_r0pre_l[BH];
__device__ __align__(16) __nv_bfloat16 b_f0pre_h[BH], b_f0pre_l[BH];
__device__ __align__(16) __nv_bfloat16 b_h0pre_h[BH], b_h0pre_l[BH];
// recurrence weights split: order 0=Ur0 1=Uf0 2=Uh0 3=Wr1 4=Ur1 5=Wf1 6=Uf1 7=Wh1 8=Uh1
__device__ __align__(16) __nv_bfloat16 gRW_hi[9*HH], gRW_lo[9*HH];
// output GEMM operands
__device__ __align__(16) __nv_bfloat16 gH_hi[SEQL*BH], gH_lo[SEQL*BH];
__device__ __align__(16) __nv_bfloat16 gW_hi[(size_t)VOCAB*HID], gW_lo[(size_t)VOCAB*HID];

__device__ __forceinline__ void split_store(__nv_bfloat16* hi, __nv_bfloat16* lo, int i, float v){
    __nv_bfloat16 h = __float2bfloat16_rn(v);
    hi[i] = h;
    lo[i] = __float2bfloat16_rn(v - __bfloat162float(h));
}

// ---------------- fp32 tile core (k_xin only) ----------------
template<int BM, int NTH>
__device__ __forceinline__ void gemm_core(
    const float* __restrict__ A, int lda, int aRow0, const int* __restrict__ aMap,
    const float* __restrict__ W, int ldw, int wRow0,
    int k0, int kLen,
    float* __restrict__ C, int ldc, int cRow0, int cCol0,
    float alpha, const float* __restrict__ bias)
{
    constexpr int BN  = 128;
    constexpr int BKt = 16;
    constexpr int AF4   = (BM*BKt)/(4*NTH);
    constexpr int WF4   = (BN*BKt)/(4*NTH);
    constexpr int RSTEP = NTH/4;

    __shared__ __align__(16) float sA[BKt][BM];
    __shared__ __align__(16) float sW[BKt][BN];

    const int tid = threadIdx.x;
    const int lr  = tid >> 2;
    const int kq  = tid & 3;
    const int tx  = tid & 15;
    const int ty  = tid >> 4;

    const float* aPtr[AF4];
#pragma unroll
    for (int i = 0; i < AF4; i++){
        int r  = aRow0 + lr + i*RSTEP;
        int rr = aMap ? aMap[r] : r;
        aPtr[i] = A + (size_t)rr*lda + (k0 + kq*4);
    }
    const float* wPtr[WF4];
#pragma unroll
    for (int i = 0; i < WF4; i++)
        wPtr[i] = W + (size_t)(wRow0 + lr + i*RSTEP)*ldw + (k0 + kq*4);

    u64 acc[4][8];
#pragma unroll
    for (int p = 0; p < 4; p++)
#pragma unroll
        for (int n = 0; n < 8; n++) acc[p][n] = 0ull;

    for (int k = 0; k < kLen; k += BKt){
        float4 av[AF4], wv[WF4];
#pragma unroll
        for (int i = 0; i < AF4; i++) av[i] = *(const float4*)(aPtr[i] + k);
#pragma unroll
        for (int i = 0; i < WF4; i++) wv[i] = *(const float4*)(wPtr[i] + k);
        __syncthreads();
#pragma unroll
        for (int i = 0; i < AF4; i++){
            int r = lr + i*RSTEP;
            sA[kq*4+0][r] = av[i].x; sA[kq*4+1][r] = av[i].y;
            sA[kq*4+2][r] = av[i].z; sA[kq*4+3][r] = av[i].w;
        }
#pragma unroll
        for (int i = 0; i < WF4; i++){
            int r = lr + i*RSTEP;
            sW[kq*4+0][r] = wv[i].x; sW[kq*4+1][r] = wv[i].y;
            sW[kq*4+2][r] = wv[i].z; sW[kq*4+3][r] = wv[i].w;
        }
        __syncthreads();
#pragma unroll
        for (int kk = 0; kk < BKt; kk++){
            float4 aL = *(const float4*)&sA[kk][ty*4];
            float4 aH = *(const float4*)&sA[kk][BM/2 + ty*4];
            u64 ap[4] = { pk2(aL.x,aL.y), pk2(aL.z,aL.w),
                          pk2(aH.x,aH.y), pk2(aH.z,aH.w) };
            float4 b0 = *(const float4*)&sW[kk][tx*4];
            float4 b1 = *(const float4*)&sW[kk][64 + tx*4];
            float bv[8] = {b0.x,b0.y,b0.z,b0.w,b1.x,b1.y,b1.z,b1.w};
#pragma unroll
            for (int n = 0; n < 8; n++){
                u64 bd = pk2(bv[n], bv[n]);
#pragma unroll
                for (int p = 0; p < 4; p++) fma2(acc[p][n], ap[p], bd);
            }
        }
    }

    float4 bb0 = make_float4(0.f,0.f,0.f,0.f), bb1 = bb0;
    if (bias){
        bb0 = *(const float4*)&bias[cCol0 + tx*4];
        bb1 = *(const float4*)&bias[cCol0 + 64 + tx*4];
    }
#pragma unroll
    for (int p = 0; p < 4; p++){
        float2 f0 = unpk2(acc[p][0]), f1 = unpk2(acc[p][1]);
        float2 f2 = unpk2(acc[p][2]), f3 = unpk2(acc[p][3]);
        float2 f4 = unpk2(acc[p][4]), f5 = unpk2(acc[p][5]);
        float2 f6 = unpk2(acc[p][6]), f7 = unpk2(acc[p][7]);
        int rloc = ((p < 2) ? 0 : BM/2) + ty*4 + (p & 1)*2;
        size_t base0 = (size_t)(cRow0 + rloc    )*ldc + cCol0 + tx*4;
        size_t base1 = (size_t)(cRow0 + rloc + 1)*ldc + cCol0 + tx*4;
        float4 vlo0 = make_float4(alpha*f0.x+bb0.x, alpha*f1.x+bb0.y, alpha*f2.x+bb0.z, alpha*f3.x+bb0.w);
        float4 vlo1 = make_float4(alpha*f4.x+bb1.x, alpha*f5.x+bb1.y, alpha*f6.x+bb1.z, alpha*f7.x+bb1.w);
        float4 vhi0 = make_float4(alpha*f0.y+bb0.x, alpha*f1.y+bb0.y, alpha*f2.y+bb0.z, alpha*f3.y+bb0.w);
        float4 vhi1 = make_float4(alpha*f4.y+bb1.x, alpha*f5.y+bb1.y, alpha*f6.y+bb1.z, alpha*f7.y+bb1.w);
        *(float4*)&C[base0]      = vlo0;
        *(float4*)&C[base0 + 64] = vlo1;
        *(float4*)&C[base1]      = vhi0;
        *(float4*)&C[base1 + 64] = vhi1;
    }
}

// ---------------- recurrence HMMA core ----------------
// C_partial[64 x 128-tile] = A[64,kLen] * W[128,kLen]^T (split-bf16, fp32 acc)
// 4 warps, warp tile 64x32. SMEM stage: Ahi|Alo|Bhi|Blo at 80B pitch.
#define RSTAGE 30720
#define RSMEM  (2*RSTAGE)

__device__ __forceinline__ void mma_rec_core(
    const __nv_bfloat16* __restrict__ Ah, const __nv_bfloat16* __restrict__ Al,
    const __nv_bfloat16* __restrict__ Bh, const __nv_bfloat16* __restrict__ Bl,
    int k0, int kLen, float* __restrict__ Cp, int n0)
{
    extern __shared__ __align__(128) char smem[];
    const uint32_t sb = smem_u32(smem);
    const int tid  = threadIdx.x;
    const int lane = tid & 31;
    const int wn   = tid >> 5;   // 4 warps split N

    auto issue = [&](int buf, int kofs){
        uint32_t s0 = sb + buf*RSTAGE;
#pragma unroll
        for (int i = 0; i < 2; i++){     // A hi/lo: 64 rows x 4 segs
            int idx = tid + i*128, row = idx >> 2, sg = idx & 3;
            uint32_t off = (uint32_t)row*80 + sg*16;
            size_t g = (size_t)row*HID + kofs + sg*8;
            CP16(s0 +        off, Ah + g);
            CP16(s0 + 5120 + off, Al + g);
        }
#pragma unroll
        for (int i = 0; i < 4; i++){     // B hi/lo: 128 rows x 4 segs
            int idx = tid + i*128, row = idx >> 2, sg = idx & 3;
            uint32_t off = (uint32_t)row*80 + sg*16;
            size_t g = (size_t)row*HID + kofs + sg*8;
            CP16(s0 + 10240 + off, Bh + g);
            CP16(s0 + 20480 + off, Bl + g);
        }
    };

    const int rowA = (lane & 7) + ((lane >> 3) & 1)*8;
    const uint32_t aoff = (uint32_t)rowA*80 + (uint32_t)(lane >> 4)*16;
    const int rowB = (lane & 7) + (lane >> 4)*8;
    const uint32_t boff = 10240u + (uint32_t)(wn*32 + rowB)*80 + (uint32_t)((lane >> 3) & 1)*16;

    float acc[4][4][4];
#pragma unroll
    for (int mi = 0; mi < 4; mi++)
#pragma unroll
        for (int ni = 0; ni < 4; ni++)
#pragma unroll
            for (int r = 0; r < 4; r++) acc[mi][ni][r] = 0.f;

    const int nst = kLen >> 5;
    issue(0, k0); CP_COMMIT();

    for (int s = 0; s < nst; s++){
        if (s + 1 < nst){ issue((s+1)&1, k0 + (s+1)*32); CP_COMMIT(); CP_WAIT(1); }
        else CP_WAIT(0);
        __syncthreads();

        const uint32_t st = sb + (s&1)*RSTAGE;
#pragma unroll
        for (int kk = 0; kk < 2; kk++){
            uint32_t aH[4][4], aL[4][4], bH[4][2], bL[4][2];
#pragma unroll
            for (int mi = 0; mi < 4; mi++){
                ldsm4(aH[mi], st +        aoff + mi*(16*80) + kk*32);
                ldsm4(aL[mi], st + 5120 + aoff + mi*(16*80) + kk*32);
            }
#pragma unroll
            for (int p = 0; p < 2; p++){
                uint32_t tr[4];
                ldsm4(tr, st +         boff + p*(16*80) + kk*32);
                bH[2*p][0]=tr[0]; bH[2*p][1]=tr[1]; bH[2*p+1][0]=tr[2]; bH[2*p+1][1]=tr[3];
                ldsm4(tr, st + 10240 + boff + p*(16*80) + kk*32);
                bL[2*p][0]=tr[0]; bL[2*p][1]=tr[1]; bL[2*p+1][0]=tr[2]; bL[2*p+1][1]=tr[3];
            }
#pragma unroll
            for (int mi = 0; mi < 4; mi++)
#pragma unroll
                for (int ni = 0; ni < 4; ni++){
                    mma_bf16(acc[mi][ni], aH[mi], bH[ni]);
                    mma_bf16(acc[mi][ni], aH[mi], bL[ni]);
                    mma_bf16(acc[mi][ni], aL[mi], bH[ni]);
                }
        }
        __syncthreads();
    }

    const int mBase = lane >> 2;
    const int nBase = n0 + wn*32 + (lane & 3)*2;
#pragma unroll
    for (int mi = 0; mi < 4; mi++)
#pragma unroll
        for (int ni = 0; ni < 4; ni++)
#pragma unroll
            for (int r = 0; r < 2; r++){
                int m = mBase + mi*16 + r*8;
                float2 v = make_float2(acc[mi][ni][2*r], acc[mi][ni][2*r+1]);
                *(float2*)&Cp[(size_t)m*HID + nBase + ni*8] = v;
            }
}

// ---------------- small kernels ----------------
__global__ void k_init(const float* __restrict__ hid){
    int i = blockIdx.x*blockDim.x + threadIdx.x;
    if (i < BH){
        float v = hid[i];
        g_prev0[i] = v; split_store(b_prev0_h, b_prev0_l, i, v);
    } else {
        int j = i - BH;
        float v = hid[i];
        g_prev1[j] = v; split_store(b_prev1_h, b_prev1_l, j, v);
    }
}

// split out_W into bf16 hi/lo
__global__ void k_cvtW(const float* __restrict__ W){
    size_t i4 = (size_t)blockIdx.x*blockDim.x + threadIdx.x;
    float4 v = *(const float4*)(W + i4*4);
    __nv_bfloat162 hA = __floats2bfloat162_rn(v.x, v.y);
    __nv_bfloat162 hB = __floats2bfloat162_rn(v.z, v.w);
    __nv_bfloat162 lA = __floats2bfloat162_rn(v.x - __low2float(hA), v.y - __high2float(hA));
    __nv_bfloat162 lB = __floats2bfloat162_rn(v.z - __low2float(hB), v.w - __high2float(hB));
    *(__nv_bfloat162*)(gW_hi + i4*4)     = hA;
    *(__nv_bfloat162*)(gW_hi + i4*4 + 2) = hB;
    *(__nv_bfloat162*)(gW_lo + i4*4)     = lA;
    *(__nv_bfloat162*)(gW_lo + i4*4 + 2) = lB;
}

// split the 9 recurrence weight matrices
__global__ void k_cvtRW(const float* __restrict__ Ur, const float* __restrict__ Uf,
                        const float* __restrict__ Uh, const float* __restrict__ Wr1,
                        const float* __restrict__ Wf1, const float* __restrict__ Wh1){
    const float* srcs[9] = {Ur, Uf, Uh, Wr1, Ur + HH, Wf1, Uf + HH, Wh1, Uh + HH};
    int m = blockIdx.y;
    size_t i4 = (size_t)blockIdx.x*blockDim.x + threadIdx.x;
    float4 v = *(const float4*)(srcs[m] + i4*4);
    size_t o = (size_t)m*HH + i4*4;
    __nv_bfloat162 hA = __floats2bfloat162_rn(v.x, v.y);
    __nv_bfloat162 hB = __floats2bfloat162_rn(v.z, v.w);
    __nv_bfloat162 lA = __floats2bfloat162_rn(v.x - __low2float(hA), v.y - __high2float(hA));
    __nv_bfloat162 lB = __floats2bfloat162_rn(v.z - __low2float(hB), v.w - __high2float(hB));
    *(__nv_bfloat162*)(gRW_hi + o)     = hA;
    *(__nv_bfloat162*)(gRW_hi + o + 2) = hB;
    *(__nv_bfloat162*)(gRW_lo + o)     = lA;
    *(__nv_bfloat162*)(gRW_lo + o + 2) = lB;
}

// Xin[m,:] = sqrt(E) * emb[tok[m],:] @ W_in^T
__global__ void __launch_bounds__(256,2) k_xin(const int* __restrict__ toks,
                                               const float* __restrict__ emb,
                                               const float* __restrict__ Win){
    gemm_core<128,256>(emb, EMBD, blockIdx.x*128, toks,
                       Win, EMBD, blockIdx.y*128,
                       0, EMBD,
                       g_Xin, HID, blockIdx.x*128, blockIdx.y*128,
                       SQRTE, nullptr);
}

// ---------------- recurrence GEMM phases (HMMA) ----------------
// phase 1: reset/forget layer-0.  grid (8 nt, 2 gate, 8 ks), slots 0-15
__global__ void __launch_bounds__(128) k_gates0(){
    int nt = blockIdx.x, gate = blockIdx.y, ks = blockIdx.z;
    size_t wofs = (size_t)gate*HH + (size_t)nt*128*HID;
    mma_rec_core(b_prev0_h, b_prev0_l, gRW_hi + wofs, gRW_lo + wofs,
                 ks*128, 128, g_part + (size_t)(gate*8 + ks)*BH, nt*128);
}

__global__ void k_fin0(int t, const float* __restrict__ br0, const float* __restrict__ bf0){
    int i = blockIdx.x*blockDim.x + threadIdx.x;
    int n = i & (HID-1);
    float s0 = 0.f, s1 = 0.f;
#pragma unroll
    for (int ks = 0; ks < 8; ks++){
        s0 += g_part[(size_t)ks*BH + i];
        s1 += g_part[(size_t)(8+ks)*BH + i];
    }
    float xv = g_Xin[(size_t)t*BH + i];
    float rpre = xv + br0[n] + s0;
    float fpre = xv + bf0[n] + s1;
    split_store(b_r0pre_h, b_r0pre_l, i, rpre);
    split_store(b_f0pre_h, b_f0pre_l, i, fpre);
    split_store(b_rp0_h,   b_rp0_l,   i, sigmf(rpre) * g_prev0[i]);
    g_z0[i] = sigmf(fpre);
}

// phase 2: job0 htil0-U (K=1024), job1/2 fused layer-1 reset/forget (K=2048)
// grid (8 nt, 3 job, 8 ks), slots job*8+ks (0-23)
__global__ void __launch_bounds__(128) k_mid(){
    int nt = blockIdx.x, job = blockIdx.y, ks = blockIdx.z;
    const __nv_bfloat16 *Ah, *Al; int widx, k0, kLen;
    if (job == 0){ Ah = b_rp0_h; Al = b_rp0_l; widx = 2; k0 = ks*128; kLen = 128; }
    else {
        int wW = (job == 1) ? 3 : 5;   // Wr1 / Wf1
        int wU = (job == 1) ? 4 : 6;   // Ur1 / Uf1
        if (ks < 4){
            Ah = (job == 1) ? b_r0pre_h : b_f0pre_h;
            Al = (job == 1) ? b_r0pre_l : b_f0pre_l;
            widx = wW; k0 = ks*256;
        } else {
            Ah = b_prev1_h; Al = b_prev1_l;
            widx = wU; k0 = (ks-4)*256;
        }
        kLen = 256;
    }
    size_t wofs = (size_t)widx*HH + (size_t)nt*128*HID;
    mma_rec_core(Ah, Al, gRW_hi + wofs, gRW_lo + wofs,
                 k0, kLen, g_part + (size_t)(job*8 + ks)*BH, nt*128);
}

__global__ void k_fin_mid(int t, const float* __restrict__ bh0,
                          const float* __restrict__ br1, const float* __restrict__ bf1){
    int i = blockIdx.x*blockDim.x + threadIdx.x;
    int n = i & (HID-1);
    float s0 = 0.f, s1 = 0.f, s2 = 0.f;
#pragma unroll
    for (int ks = 0; ks < 8; ks++){
        s0 += g_part[(size_t)ks*BH + i];
        s1 += g_part[(size_t)(8+ks)*BH + i];
        s2 += g_part[(size_t)(16+ks)*BH + i];
    }
    float htil0 = g_Xin[(size_t)t*BH + i] + bh0[n] + s0;
    float z  = g_z0[i];
    float p0 = g_prev0[i];
    float h0 = (1.0f - z)*p0 + z*tanhf(htil0);
    g_prev0[i] = h0;
    split_store(b_prev0_h, b_prev0_l, i, h0);
    split_store(b_h0pre_h, b_h0pre_l, i, htil0);
    float r1p = s1 + br1[n];
    float f1p = s2 + bf1[n];
    float p1 = g_prev1[i];
    split_store(b_rp1_h, b_rp1_l, i, sigmf(r1p) * p1);
    g_z1[i] = sigmf(f1p);
}

// phase 3: htil0@Wh1^T + (r1*prev1)@Uh1^T fused K=2048.  grid (8 nt, 16 ks), slots 0-15
__global__ void __launch_bounds__(128) k_last(){
    int nt = blockIdx.x, ks = blockIdx.y;
    const __nv_bfloat16 *Ah, *Al; int widx, k0;
    if (ks < 8){ Ah = b_h0pre_h; Al = b_h0pre_l; widx = 7; k0 = ks*128; }
    else       { Ah = b_rp1_h;   Al = b_rp1_l;   widx = 8; k0 = (ks-8)*128; }
    size_t wofs = (size_t)widx*HH + (size_t)nt*128*HID;
    mma_rec_core(Ah, Al, gRW_hi + wofs, gRW_lo + wofs,
                 k0, 128, g_part + (size_t)ks*BH, nt*128);
}

__global__ void k_fin_last(int t, const float* __restrict__ bh1){
    int i = blockIdx.x*blockDim.x + threadIdx.x;
    int n = i & (HID-1);
    float s = 0.f;
#pragma unroll
    for (int ks = 0; ks < 16; ks++) s += g_part[(size_t)ks*BH + i];
    float htil1 = s + bh1[n];
    float z  = g_z1[i];
    float p1 = g_prev1[i];
    float h  = (1.0f - z)*p1 + z*tanhf(htil1);
    g_prev1[i] = h;
    split_store(b_prev1_h, b_prev1_l, i, h);
    split_store(gH_hi, gH_lo, (int)((size_t)t*BH + i) , h);
}

// ---------------- output GEMM (proven round-6 kernel, unchanged) ----------------
#define OSTAGE 40960
#define OSMEM  (2*OSTAGE)
#define OKIT   (HID/32)

__global__ void __launch_bounds__(256,1) k_out_mma(const float* __restrict__ outb,
                                                   float* __restrict__ logits){
    extern __shared__ __align__(128) char smem[];
    const uint32_t sb = smem_u32(smem);
    const int tid  = threadIdx.x;
    const int lane = tid & 31;
    const int wid  = tid >> 5;
    const int wm   = wid >> 2;
    const int wn   = wid & 3;
    const int m0 = blockIdx.x * 128;
    const int n0 = blockIdx.y * 128;

    const int rowg = tid >> 2;
    const int seg  = tid & 3;
    const uint32_t soff = (uint32_t)rowg*80 + seg*16;
    const __nv_bfloat16* pAh = gH_hi + (size_t)(m0 + rowg)*HID + seg*8;
    const __nv_bfloat16* pAl = gH_lo + (size_t)(m0 + rowg)*HID + seg*8;
    const __nv_bfloat16* pBh = gW_hi + (size_t)(n0 + rowg)*HID + seg*8;
    const __nv_bfloat16* pBl = gW_lo + (size_t)(n0 + rowg)*HID + seg*8;
    const size_t rstep = (size_t)64*HID;

    auto issue = [&](int buf, int k0){
        uint32_t s0 = sb + buf*OSTAGE;
        CP16(s0 +         soff,         pAh + k0);
        CP16(s0 +         soff + 64*80, pAh + k0 + rstep);
        CP16(s0 + 10240 + soff,         pAl + k0);
        CP16(s0 + 10240 + soff + 64*80, pAl + k0 + rstep);
        CP16(s0 + 20480 + soff,         pBh + k0);
        CP16(s0 + 20480 + soff + 64*80, pBh + k0 + rstep);
        CP16(s0 + 30720 + soff,         pBl + k0);
        CP16(s0 + 30720 + soff + 64*80, pBl + k0 + rstep);
    };

    const int rowA = (lane & 7) + ((lane >> 3) & 1)*8;
    const uint32_t aoff = (uint32_t)(wm*64 + rowA)*80 + (uint32_t)(lane >> 4)*16;
    const int rowB = (lane & 7) + (lane >> 4)*8;
    const uint32_t boff = 20480u + (uint32_t)(wn*32 + rowB)*80 + (uint32_t)((lane >> 3) & 1)*16;

    float acc[4][4][4];
#pragma unroll
    for (int mi = 0; mi < 4; mi++)
#pragma unroll
        for (int ni = 0; ni < 4; ni++)
#pragma unroll
            for (int r = 0; r < 4; r++) acc[mi][ni][r] = 0.f;

    issue(0, 0);
    CP_COMMIT();

    for (int s = 0; s < OKIT; s++){
        if (s + 1 < OKIT){ issue((s+1)&1, (s+1)*32); CP_COMMIT(); }
        if (s + 1 < OKIT) CP_WAIT(1); else CP_WAIT(0);
        __syncthreads();

        const uint32_t st = sb + (s&1)*OSTAGE;
#pragma unroll
        for (int kk = 0; kk < 2; kk++){
            uint32_t aH[4][4], aL[4][4], bH[4][2], bL[4][2];
#pragma unroll
            for (int mi = 0; mi < 4; mi++){
                ldsm4(aH[mi], st +         aoff + mi*(16*80) + kk*32);
                ldsm4(aL[mi], st + 10240 + aoff + mi*(16*80) + kk*32);
            }
#pragma unroll
            for (int p = 0; p < 2; p++){
                uint32_t t[4];
                ldsm4(t, st +         boff + p*(16*80) + kk*32);
                bH[2*p][0]=t[0]; bH[2*p][1]=t[1]; bH[2*p+1][0]=t[2]; bH[2*p+1][1]=t[3];
                ldsm4(t, st + 10240 + boff + p*(16*80) + kk*32);
                bL[2*p][0]=t[0]; bL[2*p][1]=t[1]; bL[2*p+1][0]=t[2]; bL[2*p+1][1]=t[3];
            }
#pragma unroll
            for (int mi = 0; mi < 4; mi++)
#pragma unroll
                for (int ni = 0; ni < 4; ni++){
                    mma_bf16(acc[mi][ni], aH[mi], bH[ni]);
                    mma_bf16(acc[mi][ni], aH[mi], bL[ni]);
                    mma_bf16(acc[mi][ni], aL[mi], bH[ni]);
                }
        }
        __syncthreads();
    }

    const int mBase = m0 + wm*64 + (lane >> 2);
    const int nBase = n0 + wn*32 + (lane & 3)*2;
    float2 bv[4];
#pragma unroll
    for (int ni = 0; ni < 4; ni++) bv[ni] = *(const float2*)&outb[nBase + ni*8];
#pragma unroll
    for (int mi = 0; mi < 4; mi++)
#pragma unroll
        for (int ni = 0; ni < 4; ni++){
#pragma unroll
            for (int r = 0; r < 2; r++){
                int m = mBase + mi*16 + r*8;
                float2 v = make_float2(acc[mi][ni][2*r] + bv[ni].x,
                                       acc[mi][ni][2*r+1] + bv[ni].y);
                *(float2*)&logits[(size_t)m*VOCAB + nBase + ni*8] = v;
            }
        }
}

__global__ void k_copy(float* __restrict__ dst){
    int i = blockIdx.x*blockDim.x + threadIdx.x;
    dst[i] = (i < BH) ? g_prev0[i] : g_prev1[i - BH];
}

// ---------------- launch ----------------
extern "C" void kernel_launch(void* const* d_in, const int* in_sizes, int n_in,
                              void* d_out, int out_size) {
    const int*   toks = (const int*)  d_in[0];
    const float* hid  = (const float*)d_in[1];
    const float* emb  = (const float*)d_in[2];
    const float* Win  = (const float*)d_in[3];
    const float* Wr1  = (const float*)d_in[4];
    const float* Wf1  = (const float*)d_in[5];
    const float* Wh1  = (const float*)d_in[6];
    const float* Ur   = (const float*)d_in[7];
    const float* br   = (const float*)d_in[8];
    const float* Uf   = (const float*)d_in[9];
    const float* bf   = (const float*)d_in[10];
    const float* Uh   = (const float*)d_in[11];
    const float* bh   = (const float*)d_in[12];
    const float* outW = (const float*)d_in[13];
    const float* outb = (const float*)d_in[14];
    float* out = (float*)d_out;

    const float *br0 = br, *br1 = br + HID;
    const float *bf0 = bf, *bf1 = bf + HID;
    const float *bh0 = bh, *bh1 = bh + HID;

    cudaFuncSetAttribute(k_out_mma, cudaFuncAttributeMaxDynamicSharedMemorySize, OSMEM);
    cudaFuncSetAttribute(k_gates0,  cudaFuncAttributeMaxDynamicSharedMemorySize, RSMEM);
    cudaFuncSetAttribute(k_mid,     cudaFuncAttributeMaxDynamicSharedMemorySize, RSMEM);
    cudaFuncSetAttribute(k_last,    cudaFuncAttributeMaxDynamicSharedMemorySize, RSMEM);

    k_init<<<2*BH/256, 256>>>(hid);
    k_cvtW<<<((size_t)VOCAB*HID/4)/256, 256>>>(outW);
    k_cvtRW<<<dim3(HH/4/256, 9), 256>>>(Ur, Uf, Uh, Wr1, Wf1, Wh1);
    k_xin<<<dim3(32,8), 256>>>(toks, emb, Win);

    for (int t = 0; t < SEQL; t++){
        k_gates0  <<<dim3(8,2,8), 128, RSMEM>>>();
        k_fin0    <<<BH/256,      256>>>(t, br0, bf0);
        k_mid     <<<dim3(8,3,8), 128, RSMEM>>>();
        k_fin_mid <<<BH/256,      256>>>(t, bh0, br1, bf1);
        k_last    <<<dim3(8,16),  128, RSMEM>>>();
        k_fin_last<<<BH/256,      256>>>(t, bh1);
    }

    k_out_mma<<<dim3(32,250), 256, OSMEM>>>(outb, out);

    if ((size_t)out_size >= LOGITS_N + 2*(size_t)BH)
        k_copy<<<2*BH/256, 256>>>(out + LOGITS_N);
}

// round 9
// speedup vs baseline: 2.0278x; 1.0183x over previous
#include <cuda_runtime.h>
#include <cuda_bf16.h>
#include <math.h>
#include <stdint.h>

// ---------------- problem constants ----------------
#define SEQL  64
#define BATCH 64
#define HID   1024
#define EMBD  1024
#define VOCAB 32000
#define BH    (BATCH*HID)            // 65536
#define LOGITS_N ((size_t)SEQL*BATCH*VOCAB)
#define SQRTE 32.0f
#define HH    (HID*HID)

typedef unsigned long long u64;

__device__ __forceinline__ float sigmf(float x){ return 1.0f/(1.0f + expf(-x)); }

// ---------------- smem / async-copy / mma helpers ----------------
__device__ __forceinline__ uint32_t smem_u32(const void* p){
    uint32_t a;
    asm("{ .reg .u64 t; cvta.to.shared.u64 t, %1; cvt.u32.u64 %0, t; }" : "=r"(a) : "l"(p));
    return a;
}
#define CP16(sa, gp) \
    asm volatile("cp.async.cg.shared.global [%0], [%1], 16;" :: "r"((uint32_t)(sa)), "l"(gp) : "memory")
#define CP_COMMIT() asm volatile("cp.async.commit_group;" ::: "memory")
#define CP_WAIT(n)  asm volatile("cp.async.wait_group %0;" :: "n"(n) : "memory")

__device__ __forceinline__ void ldsm4(uint32_t* r, uint32_t addr){
    asm volatile("ldmatrix.sync.aligned.m8n8.x4.shared.b16 {%0,%1,%2,%3}, [%4];"
        : "=r"(r[0]), "=r"(r[1]), "=r"(r[2]), "=r"(r[3]) : "r"(addr));
}
__device__ __forceinline__ void mma_bf16(float* d, const uint32_t* a, const uint32_t* b){
    asm volatile(
        "mma.sync.aligned.m16n8k16.row.col.f32.bf16.bf16.f32 "
        "{%0,%1,%2,%3}, {%4,%5,%6,%7}, {%8,%9}, {%0,%1,%2,%3};"
        : "+f"(d[0]), "+f"(d[1]), "+f"(d[2]), "+f"(d[3])
        : "r"(a[0]), "r"(a[1]), "r"(a[2]), "r"(a[3]), "r"(b[0]), "r"(b[1]));
}

// ---------------- device scratch ----------------
__device__ __align__(16) float g_Xin[SEQL*BH];
__device__ __align__(16) float g_prev0[BH];
__device__ __align__(16) float g_prev1[BH];
__device__ __align__(16) float g_z0[BH];
__device__ __align__(16) float g_z1[BH];
__device__ __align__(16) float g_part[32*BH];
// bf16 hi/lo activation operands
__device__ __align__(16) __nv_bfloat16 b_prev0_h[BH], b_prev0_l[BH];
__device__ __align__(16) __nv_bfloat16 b_prev1_h[BH], b_prev1_l[BH];
__device__ __align__(16) __nv_bfloat16 b_rp0_h[BH],   b_rp0_l[BH];
__device__ __align__(16) __nv_bfloat16 b_rp1_h[BH],   b_rp1_l[BH];
__device__ __align__(16) __nv_bfloat16 b_r0pre_h[BH], b_r0pre_l[BH];
__device__ __align__(16) __nv_bfloat16 b_f0pre_h[BH], b_f0pre_l[BH];
__device__ __align__(16) __nv_bfloat16 b_h0pre_h[BH], b_h0pre_l[BH];
// recurrence weights: 0=Ur0 1=Uf0 2=Uh0 3=Wr1 4=Ur1 5=Wf1 6=Uf1 7=Wh1 8=Uh1
__device__ __align__(16) __nv_bfloat16 gRW_hi[9*HH], gRW_lo[9*HH];
// k_xin operands
__device__ __align__(16) __nv_bfloat16 gX_hi[SEQL*BH], gX_lo[SEQL*BH];
__device__ __align__(16) __nv_bfloat16 gWin_hi[HH], gWin_lo[HH];
// output GEMM operands
__device__ __align__(16) __nv_bfloat16 gH_hi[SEQL*BH], gH_lo[SEQL*BH];
__device__ __align__(16) __nv_bfloat16 gW_hi[(size_t)VOCAB*HID], gW_lo[(size_t)VOCAB*HID];

__device__ __forceinline__ void split_store(__nv_bfloat16* hi, __nv_bfloat16* lo, size_t i, float v){
    __nv_bfloat16 h = __float2bfloat16_rn(v);
    hi[i] = h;
    lo[i] = __float2bfloat16_rn(v - __bfloat162float(h));
}
__device__ __forceinline__ void split_store4(__nv_bfloat16* hi, __nv_bfloat16* lo, size_t i, float4 v){
    __nv_bfloat162 h0 = __floats2bfloat162_rn(v.x, v.y);
    __nv_bfloat162 h1 = __floats2bfloat162_rn(v.z, v.w);
    __nv_bfloat162 l0 = __floats2bfloat162_rn(v.x - __low2float(h0),  v.y - __high2float(h0));
    __nv_bfloat162 l1 = __floats2bfloat162_rn(v.z - __low2float(h1),  v.w - __high2float(h1));
    *(__nv_bfloat162*)(hi + i)     = h0;
    *(__nv_bfloat162*)(hi + i + 2) = h1;
    *(__nv_bfloat162*)(lo + i)     = l0;
    *(__nv_bfloat162*)(lo + i + 2) = l1;
}
#define V4ADD(a,b) do{ (a).x+=(b).x; (a).y+=(b).y; (a).z+=(b).z; (a).w+=(b).w; }while(0)

// ---------------- 128x128 HMMA kernel (K=1024, split-bf16) ----------------
#define OSTAGE 40960
#define OSMEM  (2*OSTAGE)
#define OKIT   (HID/32)

__global__ void __launch_bounds__(256,1) k_mma128(
    const __nv_bfloat16* __restrict__ Ah, const __nv_bfloat16* __restrict__ Al,
    const __nv_bfloat16* __restrict__ Bh, const __nv_bfloat16* __restrict__ Bl,
    float* __restrict__ C, size_t ldc, const float* __restrict__ bias)
{
    extern __shared__ __align__(128) char smem[];
    const uint32_t sb = smem_u32(smem);
    const int tid  = threadIdx.x;
    const int lane = tid & 31;
    const int wid  = tid >> 5;
    const int wm   = wid >> 2;
    const int wn   = wid & 3;
    const int m0 = blockIdx.x * 128;
    const int n0 = blockIdx.y * 128;

    const int rowg = tid >> 2;
    const int seg  = tid & 3;
    const uint32_t soff = (uint32_t)rowg*80 + seg*16;
    const __nv_bfloat16* pAh = Ah + (size_t)(m0 + rowg)*HID + seg*8;
    const __nv_bfloat16* pAl = Al + (size_t)(m0 + rowg)*HID + seg*8;
    const __nv_bfloat16* pBh = Bh + (size_t)(n0 + rowg)*HID + seg*8;
    const __nv_bfloat16* pBl = Bl + (size_t)(n0 + rowg)*HID + seg*8;
    const size_t rstep = (size_t)64*HID;

    auto issue = [&](int buf, int k0){
        uint32_t s0 = sb + buf*OSTAGE;
        CP16(s0 +         soff,         pAh + k0);
        CP16(s0 +         soff + 64*80, pAh + k0 + rstep);
        CP16(s0 + 10240 + soff,         pAl + k0);
        CP16(s0 + 10240 + soff + 64*80, pAl + k0 + rstep);
        CP16(s0 + 20480 + soff,         pBh + k0);
        CP16(s0 + 20480 + soff + 64*80, pBh + k0 + rstep);
        CP16(s0 + 30720 + soff,         pBl + k0);
        CP16(s0 + 30720 + soff + 64*80, pBl + k0 + rstep);
    };

    const int rowA = (lane & 7) + ((lane >> 3) & 1)*8;
    const uint32_t aoff = (uint32_t)(wm*64 + rowA)*80 + (uint32_t)(lane >> 4)*16;
    const int rowB = (lane & 7) + (lane >> 4)*8;
    const uint32_t boff = 20480u + (uint32_t)(wn*32 + rowB)*80 + (uint32_t)((lane >> 3) & 1)*16;

    float acc[4][4][4];
#pragma unroll
    for (int mi = 0; mi < 4; mi++)
#pragma unroll
        for (int ni = 0; ni < 4; ni++)
#pragma unroll
            for (int r = 0; r < 4; r++) acc[mi][ni][r] = 0.f;

    issue(0, 0);
    CP_COMMIT();

    for (int s = 0; s < OKIT; s++){
        if (s + 1 < OKIT){ issue((s+1)&1, (s+1)*32); CP_COMMIT(); CP_WAIT(1); }
        else CP_WAIT(0);
        __syncthreads();

        const uint32_t st = sb + (s&1)*OSTAGE;
#pragma unroll
        for (int kk = 0; kk < 2; kk++){
            uint32_t aH[4][4], aL[4][4], bH[4][2], bL[4][2];
#pragma unroll
            for (int mi = 0; mi < 4; mi++){
                ldsm4(aH[mi], st +         aoff + mi*(16*80) + kk*32);
                ldsm4(aL[mi], st + 10240 + aoff + mi*(16*80) + kk*32);
            }
#pragma unroll
            for (int p = 0; p < 2; p++){
                uint32_t t[4];
                ldsm4(t, st +         boff + p*(16*80) + kk*32);
                bH[2*p][0]=t[0]; bH[2*p][1]=t[1]; bH[2*p+1][0]=t[2]; bH[2*p+1][1]=t[3];
                ldsm4(t, st + 10240 + boff + p*(16*80) + kk*32);
                bL[2*p][0]=t[0]; bL[2*p][1]=t[1]; bL[2*p+1][0]=t[2]; bL[2*p+1][1]=t[3];
            }
#pragma unroll
            for (int mi = 0; mi < 4; mi++)
#pragma unroll
                for (int ni = 0; ni < 4; ni++){
                    mma_bf16(acc[mi][ni], aH[mi], bH[ni]);
                    mma_bf16(acc[mi][ni], aH[mi], bL[ni]);
                    mma_bf16(acc[mi][ni], aL[mi], bH[ni]);
                }
        }
        __syncthreads();
    }

    const int mBase = m0 + wm*64 + (lane >> 2);
    const int nBase = n0 + wn*32 + (lane & 3)*2;
    float2 bv[4];
#pragma unroll
    for (int ni = 0; ni < 4; ni++)
        bv[ni] = bias ? *(const float2*)&bias[nBase + ni*8] : make_float2(0.f, 0.f);
#pragma unroll
    for (int mi = 0; mi < 4; mi++)
#pragma unroll
        for (int ni = 0; ni < 4; ni++)
#pragma unroll
            for (int r = 0; r < 2; r++){
                int m = mBase + mi*16 + r*8;
                float2 v = make_float2(acc[mi][ni][2*r] + bv[ni].x,
                                       acc[mi][ni][2*r+1] + bv[ni].y);
                *(float2*)&C[(size_t)m*ldc + nBase + ni*8] = v;
            }
}

// ---------------- recurrence HMMA core (64 x 128 tile) ----------------
#define RSTAGE 30720
#define RSMEM  (2*RSTAGE)

__device__ __forceinline__ void mma_rec_core(
    const __nv_bfloat16* __restrict__ Ah, const __nv_bfloat16* __restrict__ Al,
    const __nv_bfloat16* __restrict__ Bh, const __nv_bfloat16* __restrict__ Bl,
    int k0, int kLen, float* __restrict__ Cp, int n0)
{
    extern __shared__ __align__(128) char smem[];
    const uint32_t sb = smem_u32(smem);
    const int tid  = threadIdx.x;
    const int lane = tid & 31;
    const int wn   = tid >> 5;

    auto issue = [&](int buf, int kofs){
        uint32_t s0 = sb + buf*RSTAGE;
#pragma unroll
        for (int i = 0; i < 2; i++){
            int idx = tid + i*128, row = idx >> 2, sg = idx & 3;
            uint32_t off = (uint32_t)row*80 + sg*16;
            size_t g = (size_t)row*HID + kofs + sg*8;
            CP16(s0 +        off, Ah + g);
            CP16(s0 + 5120 + off, Al + g);
        }
#pragma unroll
        for (int i = 0; i < 4; i++){
            int idx = tid + i*128, row = idx >> 2, sg = idx & 3;
            uint32_t off = (uint32_t)row*80 + sg*16;
            size_t g = (size_t)row*HID + kofs + sg*8;
            CP16(s0 + 10240 + off, Bh + g);
            CP16(s0 + 20480 + off, Bl + g);
        }
    };

    const int rowA = (lane & 7) + ((lane >> 3) & 1)*8;
    const uint32_t aoff = (uint32_t)rowA*80 + (uint32_t)(lane >> 4)*16;
    const int rowB = (lane & 7) + (lane >> 4)*8;
    const uint32_t boff = 10240u + (uint32_t)(wn*32 + rowB)*80 + (uint32_t)((lane >> 3) & 1)*16;

    float acc[4][4][4];
#pragma unroll
    for (int mi = 0; mi < 4; mi++)
#pragma unroll
        for (int ni = 0; ni < 4; ni++)
#pragma unroll
            for (int r = 0; r < 4; r++) acc[mi][ni][r] = 0.f;

    const int nst = kLen >> 5;
    issue(0, k0); CP_COMMIT();

    for (int s = 0; s < nst; s++){
        if (s + 1 < nst){ issue((s+1)&1, k0 + (s+1)*32); CP_COMMIT(); CP_WAIT(1); }
        else CP_WAIT(0);
        __syncthreads();

        const uint32_t st = sb + (s&1)*RSTAGE;
#pragma unroll
        for (int kk = 0; kk < 2; kk++){
            uint32_t aH[4][4], aL[4][4], bH[4][2], bL[4][2];
#pragma unroll
            for (int mi = 0; mi < 4; mi++){
                ldsm4(aH[mi], st +        aoff + mi*(16*80) + kk*32);
                ldsm4(aL[mi], st + 5120 + aoff + mi*(16*80) + kk*32);
            }
#pragma unroll
            for (int p = 0; p < 2; p++){
                uint32_t tr[4];
                ldsm4(tr, st +         boff + p*(16*80) + kk*32);
                bH[2*p][0]=tr[0]; bH[2*p][1]=tr[1]; bH[2*p+1][0]=tr[2]; bH[2*p+1][1]=tr[3];
                ldsm4(tr, st + 10240 + boff + p*(16*80) + kk*32);
                bL[2*p][0]=tr[0]; bL[2*p][1]=tr[1]; bL[2*p+1][0]=tr[2]; bL[2*p+1][1]=tr[3];
            }
#pragma unroll
            for (int mi = 0; mi < 4; mi++)
#pragma unroll
                for (int ni = 0; ni < 4; ni++){
                    mma_bf16(acc[mi][ni], aH[mi], bH[ni]);
                    mma_bf16(acc[mi][ni], aH[mi], bL[ni]);
                    mma_bf16(acc[mi][ni], aL[mi], bH[ni]);
                }
        }
        __syncthreads();
    }

    const int mBase = lane >> 2;
    const int nBase = n0 + wn*32 + (lane & 3)*2;
#pragma unroll
    for (int mi = 0; mi < 4; mi++)
#pragma unroll
        for (int ni = 0; ni < 4; ni++)
#pragma unroll
            for (int r = 0; r < 2; r++){
                int m = mBase + mi*16 + r*8;
                float2 v = make_float2(acc[mi][ni][2*r], acc[mi][ni][2*r+1]);
                *(float2*)&Cp[(size_t)m*HID + nBase + ni*8] = v;
            }
}

// gates0 tile body: slot 16 + gate*8 + ks
__device__ __forceinline__ void gates0_body(int nt, int gate, int ks){
    size_t wofs = (size_t)gate*HH + (size_t)nt*128*HID;
    mma_rec_core(b_prev0_h, b_prev0_l, gRW_hi + wofs, gRW_lo + wofs,
                 ks*128, 128, g_part + (size_t)(16 + gate*8 + ks)*BH, nt*128);
}
// last tile body: slot ks (0-15)
__device__ __forceinline__ void last_body(int nt, int ks){
    const __nv_bfloat16 *Ah, *Al; int widx, k0;
    if (ks < 8){ Ah = b_h0pre_h; Al = b_h0pre_l; widx = 7; k0 = ks*128; }
    else       { Ah = b_rp1_h;   Al = b_rp1_l;   widx = 8; k0 = (ks-8)*128; }
    size_t wofs = (size_t)widx*HH + (size_t)nt*128*HID;
    mma_rec_core(Ah, Al, gRW_hi + wofs, gRW_lo + wofs,
                 k0, 128, g_part + (size_t)ks*BH, nt*128);
}

// ---------------- conversion kernels ----------------
__global__ void k_init(const float* __restrict__ hid){
    int i = blockIdx.x*blockDim.x + threadIdx.x;
    if (i < BH){
        float v = hid[i];
        g_prev0[i] = v; split_store(b_prev0_h, b_prev0_l, i, v);
    } else {
        int j = i - BH;
        float v = hid[i];
        g_prev1[j] = v; split_store(b_prev1_h, b_prev1_l, j, v);
    }
}

// generic fp32 -> split bf16 (dst pointers resolved via cudaGetSymbolAddress)
__global__ void k_split(const float* __restrict__ src,
                        __nv_bfloat16* __restrict__ hi, __nv_bfloat16* __restrict__ lo){
    size_t i4 = (size_t)blockIdx.x*blockDim.x + threadIdx.x;
    float4 v = *(const float4*)(src + i4*4);
    split_store4(hi, lo, i4*4, v);
}

// 9 recurrence weights
__global__ void k_cvtRW(const float* __restrict__ Ur, const float* __restrict__ Uf,
                        const float* __restrict__ Uh, const float* __restrict__ Wr1,
                        const float* __restrict__ Wf1, const float* __restrict__ Wh1){
    const float* srcs[9] = {Ur, Uf, Uh, Wr1, Ur + HH, Wf1, Uf + HH, Wh1, Uh + HH};
    int m = blockIdx.y;
    size_t i4 = (size_t)blockIdx.x*blockDim.x + threadIdx.x;
    float4 v = *(const float4*)(srcs[m] + i4*4);
    split_store4(gRW_hi, gRW_lo, (size_t)m*HH + i4*4, v);
}

// gather emb rows, scale by sqrt(E), split
__global__ void k_cvtX(const int* __restrict__ toks, const float* __restrict__ emb){
    size_t i4 = (size_t)blockIdx.x*blockDim.x + threadIdx.x;
    int row  = (int)(i4 >> 8);
    int colq = (int)(i4 & 255);
    int tok  = toks[row];
    float4 v = *(const float4*)(emb + (size_t)tok*EMBD + colq*4);
    v.x *= SQRTE; v.y *= SQRTE; v.z *= SQRTE; v.w *= SQRTE;
    split_store4(gX_hi, gX_lo, i4*4, v);
}

// ---------------- recurrence phase kernels ----------------
__global__ void __launch_bounds__(128) k_gates0(){
    int b = blockIdx.x;
    gates0_body((b>>3)&7, b>>6, b&7);
}

// phase 2: grid (8 nt, 3 job, 8 ks) -> slots 0-23
__global__ void __launch_bounds__(128) k_mid(){
    int nt = blockIdx.x, job = blockIdx.y, ks = blockIdx.z;
    const __nv_bfloat16 *Ah, *Al; int widx, k0, kLen;
    if (job == 0){ Ah = b_rp0_h; Al = b_rp0_l; widx = 2; k0 = ks*128; kLen = 128; }
    else {
        int wW = (job == 1) ? 3 : 5;
        int wU = (job == 1) ? 4 : 6;
        if (ks < 4){
            Ah = (job == 1) ? b_r0pre_h : b_f0pre_h;
            Al = (job == 1) ? b_r0pre_l : b_f0pre_l;
            widx = wW; k0 = ks*256;
        } else {
            Ah = b_prev1_h; Al = b_prev1_l;
            widx = wU; k0 = (ks-4)*256;
        }
        kLen = 256;
    }
    size_t wofs = (size_t)widx*HH + (size_t)nt*128*HID;
    mma_rec_core(Ah, Al, gRW_hi + wofs, gRW_lo + wofs,
                 k0, kLen, g_part + (size_t)(job*8 + ks)*BH, nt*128);
}

// phase B: k_last(t) [CTAs 0-127] + gates0(t+1) [CTAs 128-255]
__global__ void __launch_bounds__(128) k_phaseB(){
    int b = blockIdx.x;
    if (b < 128) last_body(b>>4, b&15);
    else { int r = b - 128; gates0_body((r>>3)&7, r>>6, r&7); }
}

// ---------------- fin kernels (float4) ----------------
__global__ void k_fin0(int t, const float* __restrict__ br0, const float* __restrict__ bf0){
    size_t i = ((size_t)blockIdx.x*blockDim.x + threadIdx.x)*4;
    int n = (int)(i & (HID-1));
    float4 s0 = make_float4(0,0,0,0), s1 = s0;
#pragma unroll
    for (int ks = 0; ks < 8; ks++){
        float4 a = *(const float4*)&g_part[(size_t)(16+ks)*BH + i]; V4ADD(s0, a);
        float4 b = *(const float4*)&g_part[(size_t)(24+ks)*BH + i]; V4ADD(s1, b);
    }
    float4 xv = *(const float4*)&g_Xin[(size_t)t*BH + i];
    float4 bR = *(const float4*)&br0[n];
    float4 bF = *(const float4*)&bf0[n];
    float4 p0 = *(const float4*)&g_prev0[i];
    float4 rp = make_float4(xv.x+bR.x+s0.x, xv.y+bR.y+s0.y, xv.z+bR.z+s0.z, xv.w+bR.w+s0.w);
    float4 fp = make_float4(xv.x+bF.x+s1.x, xv.y+bF.y+s1.y, xv.z+bF.z+s1.z, xv.w+bF.w+s1.w);
    split_store4(b_r0pre_h, b_r0pre_l, i, rp);
    split_store4(b_f0pre_h, b_f0pre_l, i, fp);
    float4 rpv = make_float4(sigmf(rp.x)*p0.x, sigmf(rp.y)*p0.y, sigmf(rp.z)*p0.z, sigmf(rp.w)*p0.w);
    split_store4(b_rp0_h, b_rp0_l, i, rpv);
    *(float4*)&g_z0[i] = make_float4(sigmf(fp.x), sigmf(fp.y), sigmf(fp.z), sigmf(fp.w));
}

__global__ void k_fin_mid(int t, const float* __restrict__ bh0,
                          const float* __restrict__ br1, const float* __restrict__ bf1){
    size_t i = ((size_t)blockIdx.x*blockDim.x + threadIdx.x)*4;
    int n = (int)(i & (HID-1));
    float4 s0 = make_float4(0,0,0,0), s1 = s0, s2 = s0;
#pragma unroll
    for (int ks = 0; ks < 8; ks++){
        float4 a = *(const float4*)&g_part[(size_t)ks*BH + i];      V4ADD(s0, a);
        float4 b = *(const float4*)&g_part[(size_t)(8+ks)*BH + i];  V4ADD(s1, b);
        float4 c = *(const float4*)&g_part[(size_t)(16+ks)*BH + i]; V4ADD(s2, c);
    }
    float4 xv = *(const float4*)&g_Xin[(size_t)t*BH + i];
    float4 bH = *(const float4*)&bh0[n];
    float4 ht = make_float4(xv.x+bH.x+s0.x, xv.y+bH.y+s0.y, xv.z+bH.z+s0.z, xv.w+bH.w+s0.w);
    float4 z  = *(const float4*)&g_z0[i];
    float4 p0 = *(const float4*)&g_prev0[i];
    float4 h0 = make_float4((1.f-z.x)*p0.x + z.x*tanhf(ht.x),
                            (1.f-z.y)*p0.y + z.y*tanhf(ht.y),
                            (1.f-z.z)*p0.z + z.z*tanhf(ht.z),
                            (1.f-z.w)*p0.w + z.w*tanhf(ht.w));
    *(float4*)&g_prev0[i] = h0;
    split_store4(b_prev0_h, b_prev0_l, i, h0);
    split_store4(b_h0pre_h, b_h0pre_l, i, ht);
    float4 bR = *(const float4*)&br1[n];
    float4 bF = *(const float4*)&bf1[n];
    float4 p1 = *(const float4*)&g_prev1[i];
    float4 rp1 = make_float4(sigmf(s1.x+bR.x)*p1.x, sigmf(s1.y+bR.y)*p1.y,
                             sigmf(s1.z+bR.z)*p1.z, sigmf(s1.w+bR.w)*p1.w);
    split_store4(b_rp1_h, b_rp1_l, i, rp1);
    *(float4*)&g_z1[i] = make_float4(sigmf(s2.x+bF.x), sigmf(s2.y+bF.y),
                                     sigmf(s2.z+bF.z), sigmf(s2.w+bF.w));
}

// combined fin: fin_last(t) + fin0(t+1) (when dogates)
__global__ void k_finB(int t, int dogates, const float* __restrict__ bh1,
                       const float* __restrict__ br0, const float* __restrict__ bf0){
    size_t i = ((size_t)blockIdx.x*blockDim.x + threadIdx.x)*4;
    int n = (int)(i & (HID-1));
    float4 s = make_float4(0,0,0,0);
#pragma unroll
    for (int ks = 0; ks < 16; ks++){
        float4 a = *(const float4*)&g_part[(size_t)ks*BH + i]; V4ADD(s, a);
    }
    float4 bH = *(const float4*)&bh1[n];
    float4 z  = *(const float4*)&g_z1[i];
    float4 p1 = *(const float4*)&g_prev1[i];
    float4 h1 = make_float4((1.f-z.x)*p1.x + z.x*tanhf(s.x+bH.x),
                            (1.f-z.y)*p1.y + z.y*tanhf(s.y+bH.y),
                            (1.f-z.z)*p1.z + z.z*tanhf(s.z+bH.z),
                            (1.f-z.w)*p1.w + z.w*tanhf(s.w+bH.w));
    *(float4*)&g_prev1[i] = h1;
    split_store4(b_prev1_h, b_prev1_l, i, h1);
    split_store4(gH_hi, gH_lo, (size_t)t*BH + i, h1);
    if (dogates){
        float4 s0 = make_float4(0,0,0,0), s1 = s0;
#pragma unroll
        for (int ks = 0; ks < 8; ks++){
            float4 a = *(const float4*)&g_part[(size_t)(16+ks)*BH + i]; V4ADD(s0, a);
            float4 b = *(const float4*)&g_part[(size_t)(24+ks)*BH + i]; V4ADD(s1, b);
        }
        float4 xv = *(const float4*)&g_Xin[(size_t)(t+1)*BH + i];
        float4 bR = *(const float4*)&br0[n];
        float4 bF = *(const float4*)&bf0[n];
        float4 p0 = *(const float4*)&g_prev0[i];
        float4 rp = make_float4(xv.x+bR.x+s0.x, xv.y+bR.y+s0.y, xv.z+bR.z+s0.z, xv.w+bR.w+s0.w);
        float4 fp = make_float4(xv.x+bF.x+s1.x, xv.y+bF.y+s1.y, xv.z+bF.z+s1.z, xv.w+bF.w+s1.w);
        split_store4(b_r0pre_h, b_r0pre_l, i, rp);
        split_store4(b_f0pre_h, b_f0pre_l, i, fp);
        float4 rpv = make_float4(sigmf(rp.x)*p0.x, sigmf(rp.y)*p0.y, sigmf(rp.z)*p0.z, sigmf(rp.w)*p0.w);
        split_store4(b_rp0_h, b_rp0_l, i, rpv);
        *(float4*)&g_z0[i] = make_float4(sigmf(fp.x), sigmf(fp.y), sigmf(fp.z), sigmf(fp.w));
    }
}

__global__ void k_copy(float* __restrict__ dst){
    int i = blockIdx.x*blockDim.x + threadIdx.x;
    dst[i] = (i < BH) ? g_prev0[i] : g_prev1[i - BH];
}

// ---------------- launch ----------------
extern "C" void kernel_launch(void* const* d_in, const int* in_sizes, int n_in,
                              void* d_out, int out_size) {
    const int*   toks = (const int*)  d_in[0];
    const float* hid  = (const float*)d_in[1];
    const float* emb  = (const float*)d_in[2];
    const float* Win  = (const float*)d_in[3];
    const float* Wr1  = (const float*)d_in[4];
    const float* Wf1  = (const float*)d_in[5];
    const float* Wh1  = (const float*)d_in[6];
    const float* Ur   = (const float*)d_in[7];
    const float* br   = (const float*)d_in[8];
    const float* Uf   = (const float*)d_in[9];
    const float* bf   = (const float*)d_in[10];
    const float* Uh   = (const float*)d_in[11];
    const float* bh   = (const float*)d_in[12];
    const float* outW = (const float*)d_in[13];
    const float* outb = (const float*)d_in[14];
    float* out = (float*)d_out;

    const float *br0 = br, *br1 = br + HID;
    const float *bf0 = bf, *bf1 = bf + HID;
    const float *bh0 = bh, *bh1 = bh + HID;

    // Resolve REAL device addresses of __device__ globals (host-side symbol
    // addresses are the host shadow copies — passing those was round 8's bug).
    void *pXh, *pXl, *pWinh, *pWinl, *pHh, *pHl, *pWh, *pWl, *pXin;
    cudaGetSymbolAddress(&pXh,  gX_hi);   cudaGetSymbolAddress(&pXl,  gX_lo);
    cudaGetSymbolAddress(&pWinh, gWin_hi); cudaGetSymbolAddress(&pWinl, gWin_lo);
    cudaGetSymbolAddress(&pHh,  gH_hi);   cudaGetSymbolAddress(&pHl,  gH_lo);
    cudaGetSymbolAddress(&pWh,  gW_hi);   cudaGetSymbolAddress(&pWl,  gW_lo);
    cudaGetSymbolAddress(&pXin, g_Xin);

    cudaFuncSetAttribute(k_mma128, cudaFuncAttributeMaxDynamicSharedMemorySize, OSMEM);
    cudaFuncSetAttribute(k_gates0, cudaFuncAttributeMaxDynamicSharedMemorySize, RSMEM);
    cudaFuncSetAttribute(k_mid,    cudaFuncAttributeMaxDynamicSharedMemorySize, RSMEM);
    cudaFuncSetAttribute(k_phaseB, cudaFuncAttributeMaxDynamicSharedMemorySize, RSMEM);

    const int FING = BH/4/256;

    k_init<<<2*BH/256, 256>>>(hid);
    k_split<<<((size_t)VOCAB*HID/4)/256, 256>>>(outW, (__nv_bfloat16*)pWh, (__nv_bfloat16*)pWl);
    k_split<<<(HH/4)/256, 256>>>(Win, (__nv_bfloat16*)pWinh, (__nv_bfloat16*)pWinl);
    k_cvtRW<<<dim3(HH/4/256, 9), 256>>>(Ur, Uf, Uh, Wr1, Wf1, Wh1);
    k_cvtX<<<(SEQL*BATCH*EMBD/4)/256, 256>>>(toks, emb);
    // Xin = X @ Win^T  (4096 x 1024)
    k_mma128<<<dim3(32,8), 256, OSMEM>>>((__nv_bfloat16*)pXh, (__nv_bfloat16*)pXl,
                                         (__nv_bfloat16*)pWinh, (__nv_bfloat16*)pWinl,
                                         (float*)pXin, HID, nullptr);

    // prologue: gates for t=0
    k_gates0<<<128, 128, RSMEM>>>();
    k_fin0<<<FING, 256>>>(0, br0, bf0);

    for (int t = 0; t < SEQL; t++){
        int dg = (t < SEQL-1) ? 1 : 0;
        k_mid    <<<dim3(8,3,8), 128, RSMEM>>>();
        k_fin_mid<<<FING, 256>>>(t, bh0, br1, bf1);
        k_phaseB <<<dg ? 256 : 128, 128, RSMEM>>>();
        k_finB   <<<FING, 256>>>(t, dg, bh1, br0, bf0);
    }

    // logits = H @ outW^T + outb
    k_mma128<<<dim3(32,250), 256, OSMEM>>>((__nv_bfloat16*)pHh, (__nv_bfloat16*)pHl,
                                           (__nv_bfloat16*)pWh, (__nv_bfloat16*)pWl,
                                           out, VOCAB, outb);

    if ((size_t)out_size >= LOGITS_N + 2*(size_t)BH)
        k_copy<<<2*BH/256, 256>>>(out + LOGITS_N);
}

// round 10
// speedup vs baseline: 2.0536x; 1.0128x over previous
#include <cuda_runtime.h>
#include <cuda_bf16.h>
#include <math.h>
#include <stdint.h>

// ---------------- problem constants ----------------
#define SEQL  64
#define BATCH 64
#define HID   1024
#define EMBD  1024
#define VOCAB 32000
#define BH    (BATCH*HID)            // 65536
#define LOGITS_N ((size_t)SEQL*BATCH*VOCAB)
#define SQRTE 32.0f
#define HH    (HID*HID)
#define NCTA  128                    // persistent grid (<=148 SMs -> always co-resident)

typedef unsigned long long u64;

__device__ __forceinline__ float sigmf(float x){ return 1.0f/(1.0f + expf(-x)); }

// ---------------- smem / async-copy / mma helpers ----------------
__device__ __forceinline__ uint32_t smem_u32(const void* p){
    uint32_t a;
    asm("{ .reg .u64 t; cvta.to.shared.u64 t, %1; cvt.u32.u64 %0, t; }" : "=r"(a) : "l"(p));
    return a;
}
#define CP16(sa, gp) \
    asm volatile("cp.async.cg.shared.global [%0], [%1], 16;" :: "r"((uint32_t)(sa)), "l"(gp) : "memory")
#define CP_COMMIT() asm volatile("cp.async.commit_group;" ::: "memory")
#define CP_WAIT(n)  asm volatile("cp.async.wait_group %0;" :: "n"(n) : "memory")

__device__ __forceinline__ void ldsm4(uint32_t* r, uint32_t addr){
    asm volatile("ldmatrix.sync.aligned.m8n8.x4.shared.b16 {%0,%1,%2,%3}, [%4];"
        : "=r"(r[0]), "=r"(r[1]), "=r"(r[2]), "=r"(r[3]) : "r"(addr));
}
__device__ __forceinline__ void mma_bf16(float* d, const uint32_t* a, const uint32_t* b){
    asm volatile(
        "mma.sync.aligned.m16n8k16.row.col.f32.bf16.bf16.f32 "
        "{%0,%1,%2,%3}, {%4,%5,%6,%7}, {%8,%9}, {%0,%1,%2,%3};"
        : "+f"(d[0]), "+f"(d[1]), "+f"(d[2]), "+f"(d[3])
        : "r"(a[0]), "r"(a[1]), "r"(a[2]), "r"(a[3]), "r"(b[0]), "r"(b[1]));
}

// ---------------- device scratch ----------------
__device__ __align__(16) float g_Xin[SEQL*BH];
__device__ __align__(16) float g_prev0[BH];
__device__ __align__(16) float g_prev1[BH];
__device__ __align__(16) float g_z0[BH];
__device__ __align__(16) float g_z1[BH];
__device__ __align__(16) float g_part[32*BH];
// bf16 hi/lo activation operands
__device__ __align__(16) __nv_bfloat16 b_prev0_h[BH], b_prev0_l[BH];
__device__ __align__(16) __nv_bfloat16 b_prev1_h[BH], b_prev1_l[BH];
__device__ __align__(16) __nv_bfloat16 b_rp0_h[BH],   b_rp0_l[BH];
__device__ __align__(16) __nv_bfloat16 b_rp1_h[BH],   b_rp1_l[BH];
__device__ __align__(16) __nv_bfloat16 b_r0pre_h[BH], b_r0pre_l[BH];
__device__ __align__(16) __nv_bfloat16 b_f0pre_h[BH], b_f0pre_l[BH];
__device__ __align__(16) __nv_bfloat16 b_h0pre_h[BH], b_h0pre_l[BH];
// recurrence weights: 0=Ur0 1=Uf0 2=Uh0 3=Wr1 4=Ur1 5=Wf1 6=Uf1 7=Wh1 8=Uh1
__device__ __align__(16) __nv_bfloat16 gRW_hi[9*HH], gRW_lo[9*HH];
// k_xin operands
__device__ __align__(16) __nv_bfloat16 gX_hi[SEQL*BH], gX_lo[SEQL*BH];
__device__ __align__(16) __nv_bfloat16 gWin_hi[HH], gWin_lo[HH];
// output GEMM operands
__device__ __align__(16) __nv_bfloat16 gH_hi[SEQL*BH], gH_lo[SEQL*BH];
__device__ __align__(16) __nv_bfloat16 gW_hi[(size_t)VOCAB*HID], gW_lo[(size_t)VOCAB*HID];

// grid barrier state (monotone generation -> graph-replay safe)
__device__ unsigned g_barCnt = 0;
__device__ volatile unsigned g_barGen = 0;

__device__ __forceinline__ void gridbar(){
    __threadfence();                 // every thread's stores visible at L2
    __syncthreads();
    if (threadIdx.x == 0){
        unsigned g = g_barGen;
        if (atomicAdd(&g_barCnt, 1u) == NCTA - 1u){
            g_barCnt = 0;
            __threadfence();
            g_barGen = g + 1u;
        } else {
            while (g_barGen == g) { }
        }
        __threadfence();             // acquire
    }
    __syncthreads();
}

__device__ __forceinline__ void split_store(__nv_bfloat16* hi, __nv_bfloat16* lo, size_t i, float v){
    __nv_bfloat16 h = __float2bfloat16_rn(v);
    hi[i] = h;
    lo[i] = __float2bfloat16_rn(v - __bfloat162float(h));
}
__device__ __forceinline__ void split_store4(__nv_bfloat16* hi, __nv_bfloat16* lo, size_t i, float4 v){
    __nv_bfloat162 h0 = __floats2bfloat162_rn(v.x, v.y);
    __nv_bfloat162 h1 = __floats2bfloat162_rn(v.z, v.w);
    __nv_bfloat162 l0 = __floats2bfloat162_rn(v.x - __low2float(h0),  v.y - __high2float(h0));
    __nv_bfloat162 l1 = __floats2bfloat162_rn(v.z - __low2float(h1),  v.w - __high2float(h1));
    *(__nv_bfloat162*)(hi + i)     = h0;
    *(__nv_bfloat162*)(hi + i + 2) = h1;
    *(__nv_bfloat162*)(lo + i)     = l0;
    *(__nv_bfloat162*)(lo + i + 2) = l1;
}
#define V4ADD(a,b) do{ (a).x+=(b).x; (a).y+=(b).y; (a).z+=(b).z; (a).w+=(b).w; }while(0)

// ---------------- 128x128 HMMA kernel (K=1024, split-bf16) ----------------
#define OSTAGE 40960
#define OSMEM  (2*OSTAGE)
#define OKIT   (HID/32)

__global__ void __launch_bounds__(256,1) k_mma128(
    const __nv_bfloat16* __restrict__ Ah, const __nv_bfloat16* __restrict__ Al,
    const __nv_bfloat16* __restrict__ Bh, const __nv_bfloat16* __restrict__ Bl,
    float* __restrict__ C, size_t ldc, const float* __restrict__ bias)
{
    extern __shared__ __align__(128) char smem[];
    const uint32_t sb = smem_u32(smem);
    const int tid  = threadIdx.x;
    const int lane = tid & 31;
    const int wid  = tid >> 5;
    const int wm   = wid >> 2;
    const int wn   = wid & 3;
    const int m0 = blockIdx.x * 128;
    const int n0 = blockIdx.y * 128;

    const int rowg = tid >> 2;
    const int seg  = tid & 3;
    const uint32_t soff = (uint32_t)rowg*80 + seg*16;
    const __nv_bfloat16* pAh = Ah + (size_t)(m0 + rowg)*HID + seg*8;
    const __nv_bfloat16* pAl = Al + (size_t)(m0 + rowg)*HID + seg*8;
    const __nv_bfloat16* pBh = Bh + (size_t)(n0 + rowg)*HID + seg*8;
    const __nv_bfloat16* pBl = Bl + (size_t)(n0 + rowg)*HID + seg*8;
    const size_t rstep = (size_t)64*HID;

    auto issue = [&](int buf, int k0){
        uint32_t s0 = sb + buf*OSTAGE;
        CP16(s0 +         soff,         pAh + k0);
        CP16(s0 +         soff + 64*80, pAh + k0 + rstep);
        CP16(s0 + 10240 + soff,         pAl + k0);
        CP16(s0 + 10240 + soff + 64*80, pAl + k0 + rstep);
        CP16(s0 + 20480 + soff,         pBh + k0);
        CP16(s0 + 20480 + soff + 64*80, pBh + k0 + rstep);
        CP16(s0 + 30720 + soff,         pBl + k0);
        CP16(s0 + 30720 + soff + 64*80, pBl + k0 + rstep);
    };

    const int rowA = (lane & 7) + ((lane >> 3) & 1)*8;
    const uint32_t aoff = (uint32_t)(wm*64 + rowA)*80 + (uint32_t)(lane >> 4)*16;
    const int rowB = (lane & 7) + (lane >> 4)*8;
    const uint32_t boff = 20480u + (uint32_t)(wn*32 + rowB)*80 + (uint32_t)((lane >> 3) & 1)*16;

    float acc[4][4][4];
#pragma unroll
    for (int mi = 0; mi < 4; mi++)
#pragma unroll
        for (int ni = 0; ni < 4; ni++)
#pragma unroll
            for (int r = 0; r < 4; r++) acc[mi][ni][r] = 0.f;

    issue(0, 0);
    CP_COMMIT();

    for (int s = 0; s < OKIT; s++){
        if (s + 1 < OKIT){ issue((s+1)&1, (s+1)*32); CP_COMMIT(); CP_WAIT(1); }
        else CP_WAIT(0);
        __syncthreads();

        const uint32_t st = sb + (s&1)*OSTAGE;
#pragma unroll
        for (int kk = 0; kk < 2; kk++){
            uint32_t aH[4][4], aL[4][4], bH[4][2], bL[4][2];
#pragma unroll
            for (int mi = 0; mi < 4; mi++){
                ldsm4(aH[mi], st +         aoff + mi*(16*80) + kk*32);
                ldsm4(aL[mi], st + 10240 + aoff + mi*(16*80) + kk*32);
            }
#pragma unroll
            for (int p = 0; p < 2; p++){
                uint32_t t[4];
                ldsm4(t, st +         boff + p*(16*80) + kk*32);
                bH[2*p][0]=t[0]; bH[2*p][1]=t[1]; bH[2*p+1][0]=t[2]; bH[2*p+1][1]=t[3];
                ldsm4(t, st + 10240 + boff + p*(16*80) + kk*32);
                bL[2*p][0]=t[0]; bL[2*p][1]=t[1]; bL[2*p+1][0]=t[2]; bL[2*p+1][1]=t[3];
            }
#pragma unroll
            for (int mi = 0; mi < 4; mi++)
#pragma unroll
                for (int ni = 0; ni < 4; ni++){
                    mma_bf16(acc[mi][ni], aH[mi], bH[ni]);
                    mma_bf16(acc[mi][ni], aH[mi], bL[ni]);
                    mma_bf16(acc[mi][ni], aL[mi], bH[ni]);
                }
        }
        __syncthreads();
    }

    const int mBase = m0 + wm*64 + (lane >> 2);
    const int nBase = n0 + wn*32 + (lane & 3)*2;
    float2 bv[4];
#pragma unroll
    for (int ni = 0; ni < 4; ni++)
        bv[ni] = bias ? *(const float2*)&bias[nBase + ni*8] : make_float2(0.f, 0.f);
#pragma unroll
    for (int mi = 0; mi < 4; mi++)
#pragma unroll
        for (int ni = 0; ni < 4; ni++)
#pragma unroll
            for (int r = 0; r < 2; r++){
                int m = mBase + mi*16 + r*8;
                float2 v = make_float2(acc[mi][ni][2*r] + bv[ni].x,
                                       acc[mi][ni][2*r+1] + bv[ni].y);
                *(float2*)&C[(size_t)m*ldc + nBase + ni*8] = v;
            }
}

// ---------------- recurrence HMMA core (64 x 128 tile) ----------------
#define RSTAGE 30720
#define RSMEM  (2*RSTAGE)

__device__ __noinline__ void mma_rec_core(
    const __nv_bfloat16* __restrict__ Ah, const __nv_bfloat16* __restrict__ Al,
    const __nv_bfloat16* __restrict__ Bh, const __nv_bfloat16* __restrict__ Bl,
    int k0, int kLen, float* __restrict__ Cp, int n0)
{
    extern __shared__ __align__(128) char smem[];
    const uint32_t sb = smem_u32(smem);
    const int tid  = threadIdx.x;
    const int lane = tid & 31;
    const int wn   = tid >> 5;

    auto issue = [&](int buf, int kofs){
        uint32_t s0 = sb + buf*RSTAGE;
#pragma unroll
        for (int i = 0; i < 2; i++){
            int idx = tid + i*128, row = idx >> 2, sg = idx & 3;
            uint32_t off = (uint32_t)row*80 + sg*16;
            size_t g = (size_t)row*HID + kofs + sg*8;
            CP16(s0 +        off, Ah + g);
            CP16(s0 + 5120 + off, Al + g);
        }
#pragma unroll
        for (int i = 0; i < 4; i++){
            int idx = tid + i*128, row = idx >> 2, sg = idx & 3;
            uint32_t off = (uint32_t)row*80 + sg*16;
            size_t g = (size_t)row*HID + kofs + sg*8;
            CP16(s0 + 10240 + off, Bh + g);
            CP16(s0 + 20480 + off, Bl + g);
        }
    };

    const int rowA = (lane & 7) + ((lane >> 3) & 1)*8;
    const uint32_t aoff = (uint32_t)rowA*80 + (uint32_t)(lane >> 4)*16;
    const int rowB = (lane & 7) + (lane >> 4)*8;
    const uint32_t boff = 10240u + (uint32_t)(wn*32 + rowB)*80 + (uint32_t)((lane >> 3) & 1)*16;

    float acc[4][4][4];
#pragma unroll
    for (int mi = 0; mi < 4; mi++)
#pragma unroll
        for (int ni = 0; ni < 4; ni++)
#pragma unroll
            for (int r = 0; r < 4; r++) acc[mi][ni][r] = 0.f;

    const int nst = kLen >> 5;
    issue(0, k0); CP_COMMIT();

    for (int s = 0; s < nst; s++){
        if (s + 1 < nst){ issue((s+1)&1, k0 + (s+1)*32); CP_COMMIT(); CP_WAIT(1); }
        else CP_WAIT(0);
        __syncthreads();

        const uint32_t st = sb + (s&1)*RSTAGE;
#pragma unroll
        for (int kk = 0; kk < 2; kk++){
            uint32_t aH[4][4], aL[4][4], bH[4][2], bL[4][2];
#pragma unroll
            for (int mi = 0; mi < 4; mi++){
                ldsm4(aH[mi], st +        aoff + mi*(16*80) + kk*32);
                ldsm4(aL[mi], st + 5120 + aoff + mi*(16*80) + kk*32);
            }
#pragma unroll
            for (int p = 0; p < 2; p++){
                uint32_t tr[4];
                ldsm4(tr, st +         boff + p*(16*80) + kk*32);
                bH[2*p][0]=tr[0]; bH[2*p][1]=tr[1]; bH[2*p+1][0]=tr[2]; bH[2*p+1][1]=tr[3];
                ldsm4(tr, st + 10240 + boff + p*(16*80) + kk*32);
                bL[2*p][0]=tr[0]; bL[2*p][1]=tr[1]; bL[2*p+1][0]=tr[2]; bL[2*p+1][1]=tr[3];
            }
#pragma unroll
            for (int mi = 0; mi < 4; mi++)
#pragma unroll
                for (int ni = 0; ni < 4; ni++){
                    mma_bf16(acc[mi][ni], aH[mi], bH[ni]);
                    mma_bf16(acc[mi][ni], aH[mi], bL[ni]);
                    mma_bf16(acc[mi][ni], aL[mi], bH[ni]);
                }
        }
        __syncthreads();
    }

    const int mBase = lane >> 2;
    const int nBase = n0 + wn*32 + (lane & 3)*2;
#pragma unroll
    for (int mi = 0; mi < 4; mi++)
#pragma unroll
        for (int ni = 0; ni < 4; ni++)
#pragma unroll
            for (int r = 0; r < 2; r++){
                int m = mBase + mi*16 + r*8;
                float2 v = make_float2(acc[mi][ni][2*r], acc[mi][ni][2*r+1]);
                *(float2*)&Cp[(size_t)m*HID + nBase + ni*8] = v;
            }
}

// job bodies ---------------------------------------------------------------
__device__ __forceinline__ void gates0_body(int nt, int gate, int ks){
    size_t wofs = (size_t)gate*HH + (size_t)nt*128*HID;
    mma_rec_core(b_prev0_h, b_prev0_l, gRW_hi + wofs, gRW_lo + wofs,
                 ks*128, 128, g_part + (size_t)(16 + gate*8 + ks)*BH, nt*128);
}
__device__ __forceinline__ void last_body(int nt, int ks){
    const __nv_bfloat16 *Ah, *Al; int widx, k0;
    if (ks < 8){ Ah = b_h0pre_h; Al = b_h0pre_l; widx = 7; k0 = ks*128; }
    else       { Ah = b_rp1_h;   Al = b_rp1_l;   widx = 8; k0 = (ks-8)*128; }
    size_t wofs = (size_t)widx*HH + (size_t)nt*128*HID;
    mma_rec_core(Ah, Al, gRW_hi + wofs, gRW_lo + wofs,
                 k0, 128, g_part + (size_t)ks*BH, nt*128);
}
__device__ __forceinline__ void mid_job(int j){   // j in [0,192)
    int job = j >> 6;          // 0,1,2
    int r   = j & 63;
    int nt  = r & 7;
    int ks  = r >> 3;          // 0..7
    const __nv_bfloat16 *Ah, *Al; int widx, k0, kLen;
    if (job == 0){ Ah = b_rp0_h; Al = b_rp0_l; widx = 2; k0 = ks*128; kLen = 128; }
    else {
        int wW = (job == 1) ? 3 : 5;
        int wU = (job == 1) ? 4 : 6;
        if (ks < 4){
            Ah = (job == 1) ? b_r0pre_h : b_f0pre_h;
            Al = (job == 1) ? b_r0pre_l : b_f0pre_l;
            widx = wW; k0 = ks*256;
        } else {
            Ah = b_prev1_h; Al = b_prev1_l;
            widx = wU; k0 = (ks-4)*256;
        }
        kLen = 256;
    }
    size_t wofs = (size_t)widx*HH + (size_t)nt*128*HID;
    mma_rec_core(Ah, Al, gRW_hi + wofs, gRW_lo + wofs,
                 k0, kLen, g_part + (size_t)(job*8 + ks)*BH, nt*128);
}

// fin device functions (1 float4 item per thread; __ldcg bypasses stale L1) --
__device__ __forceinline__ void fin0_one(size_t i, int t,
                                         const float* br0, const float* bf0){
    int n = (int)(i & (HID-1));
    float4 s0 = make_float4(0,0,0,0), s1 = s0;
#pragma unroll
    for (int ks = 0; ks < 8; ks++){
        float4 a = __ldcg((const float4*)&g_part[(size_t)(16+ks)*BH + i]); V4ADD(s0, a);
        float4 b = __ldcg((const float4*)&g_part[(size_t)(24+ks)*BH + i]); V4ADD(s1, b);
    }
    float4 xv = __ldcg((const float4*)&g_Xin[(size_t)t*BH + i]);
    float4 bR = *(const float4*)&br0[n];
    float4 bF = *(const float4*)&bf0[n];
    float4 p0 = __ldcg((const float4*)&g_prev0[i]);
    float4 rp = make_float4(xv.x+bR.x+s0.x, xv.y+bR.y+s0.y, xv.z+bR.z+s0.z, xv.w+bR.w+s0.w);
    float4 fp = make_float4(xv.x+bF.x+s1.x, xv.y+bF.y+s1.y, xv.z+bF.z+s1.z, xv.w+bF.w+s1.w);
    split_store4(b_r0pre_h, b_r0pre_l, i, rp);
    split_store4(b_f0pre_h, b_f0pre_l, i, fp);
    float4 rpv = make_float4(sigmf(rp.x)*p0.x, sigmf(rp.y)*p0.y, sigmf(rp.z)*p0.z, sigmf(rp.w)*p0.w);
    split_store4(b_rp0_h, b_rp0_l, i, rpv);
    *(float4*)&g_z0[i] = make_float4(sigmf(fp.x), sigmf(fp.y), sigmf(fp.z), sigmf(fp.w));
}

__device__ __forceinline__ void fin_mid_one(size_t i, int t, const float* bh0,
                                            const float* br1, const float* bf1){
    int n = (int)(i & (HID-1));
    float4 s0 = make_float4(0,0,0,0), s1 = s0, s2 = s0;
#pragma unroll
    for (int ks = 0; ks < 8; ks++){
        float4 a = __ldcg((const float4*)&g_part[(size_t)ks*BH + i]);      V4ADD(s0, a);
        float4 b = __ldcg((const float4*)&g_part[(size_t)(8+ks)*BH + i]);  V4ADD(s1, b);
        float4 c = __ldcg((const float4*)&g_part[(size_t)(16+ks)*BH + i]); V4ADD(s2, c);
    }
    float4 xv = __ldcg((const float4*)&g_Xin[(size_t)t*BH + i]);
    float4 bH = *(const float4*)&bh0[n];
    float4 ht = make_float4(xv.x+bH.x+s0.x, xv.y+bH.y+s0.y, xv.z+bH.z+s0.z, xv.w+bH.w+s0.w);
    float4 z  = __ldcg((const float4*)&g_z0[i]);
    float4 p0 = __ldcg((const float4*)&g_prev0[i]);
    float4 h0 = make_float4((1.f-z.x)*p0.x + z.x*tanhf(ht.x),
                            (1.f-z.y)*p0.y + z.y*tanhf(ht.y),
                            (1.f-z.z)*p0.z + z.z*tanhf(ht.z),
                            (1.f-z.w)*p0.w + z.w*tanhf(ht.w));
    *(float4*)&g_prev0[i] = h0;
    split_store4(b_prev0_h, b_prev0_l, i, h0);
    split_store4(b_h0pre_h, b_h0pre_l, i, ht);
    float4 bR = *(const float4*)&br1[n];
    float4 bF = *(const float4*)&bf1[n];
    float4 p1 = __ldcg((const float4*)&g_prev1[i]);
    float4 rp1 = make_float4(sigmf(s1.x+bR.x)*p1.x, sigmf(s1.y+bR.y)*p1.y,
                             sigmf(s1.z+bR.z)*p1.z, sigmf(s1.w+bR.w)*p1.w);
    split_store4(b_rp1_h, b_rp1_l, i, rp1);
    *(float4*)&g_z1[i] = make_float4(sigmf(s2.x+bF.x), sigmf(s2.y+bF.y),
                                     sigmf(s2.z+bF.z), sigmf(s2.w+bF.w));
}

__device__ __forceinline__ void finB_one(size_t i, int t, int dogates,
                                         const float* bh1, const float* br0, const float* bf0){
    int n = (int)(i & (HID-1));
    float4 s = make_float4(0,0,0,0);
#pragma unroll
    for (int ks = 0; ks < 16; ks++){
        float4 a = __ldcg((const float4*)&g_part[(size_t)ks*BH + i]); V4ADD(s, a);
    }
    float4 bH = *(const float4*)&bh1[n];
    float4 z  = __ldcg((const float4*)&g_z1[i]);
    float4 p1 = __ldcg((const float4*)&g_prev1[i]);
    float4 h1 = make_float4((1.f-z.x)*p1.x + z.x*tanhf(s.x+bH.x),
                            (1.f-z.y)*p1.y + z.y*tanhf(s.y+bH.y),
                            (1.f-z.z)*p1.z + z.z*tanhf(s.z+bH.z),
                            (1.f-z.w)*p1.w + z.w*tanhf(s.w+bH.w));
    *(float4*)&g_prev1[i] = h1;
    split_store4(b_prev1_h, b_prev1_l, i, h1);
    split_store4(gH_hi, gH_lo, (size_t)t*BH + i, h1);
    if (dogates){
        float4 s0 = make_float4(0,0,0,0), s1 = s0;
#pragma unroll
        for (int ks = 0; ks < 8; ks++){
            float4 a = __ldcg((const float4*)&g_part[(size_t)(16+ks)*BH + i]); V4ADD(s0, a);
            float4 b = __ldcg((const float4*)&g_part[(size_t)(24+ks)*BH + i]); V4ADD(s1, b);
        }
        float4 xv = __ldcg((const float4*)&g_Xin[(size_t)(t+1)*BH + i]);
        float4 bR = *(const float4*)&br0[n];
        float4 bF = *(const float4*)&bf0[n];
        float4 p0 = __ldcg((const float4*)&g_prev0[i]);
        float4 rp = make_float4(xv.x+bR.x+s0.x, xv.y+bR.y+s0.y, xv.z+bR.z+s0.z, xv.w+bR.w+s0.w);
        float4 fp = make_float4(xv.x+bF.x+s1.x, xv.y+bF.y+s1.y, xv.z+bF.z+s1.z, xv.w+bF.w+s1.w);
        split_store4(b_r0pre_h, b_r0pre_l, i, rp);
        split_store4(b_f0pre_h, b_f0pre_l, i, fp);
        float4 rpv = make_float4(sigmf(rp.x)*p0.x, sigmf(rp.y)*p0.y, sigmf(rp.z)*p0.z, sigmf(rp.w)*p0.w);
        split_store4(b_rp0_h, b_rp0_l, i, rpv);
        *(float4*)&g_z0[i] = make_float4(sigmf(fp.x), sigmf(fp.y), sigmf(fp.z), sigmf(fp.w));
    }
}

// ---------------- persistent recurrence kernel ----------------
__global__ void __launch_bounds__(128) k_recur(
    const float* __restrict__ br0, const float* __restrict__ bf0,
    const float* __restrict__ bh0, const float* __restrict__ br1,
    const float* __restrict__ bf1, const float* __restrict__ bh1)
{
    const int b = blockIdx.x;
    const size_t item = ((size_t)b*128 + threadIdx.x)*4;   // exactly BH/4 items

    // prologue: gates0 for t=0 (128 jobs)
    gates0_body((b>>3)&7, b>>6, b&7);
    gridbar();
    fin0_one(item, 0, br0, bf0);
    gridbar();

    for (int t = 0; t < SEQL; t++){
        // phase mid: 192 jobs over 128 CTAs
        mid_job(b);
        if (b < 64) mid_job(b + 128);
        gridbar();
        fin_mid_one(item, t, bh0, br1, bf1);
        gridbar();
        // phase B: last (128 jobs) + gates0 for t+1 (128 jobs)
        last_body(b >> 4, b & 15);
        if (t < SEQL-1) gates0_body((b>>3)&7, b>>6, b&7);
        gridbar();
        finB_one(item, t, (t < SEQL-1) ? 1 : 0, bh1, br0, bf0);
        gridbar();
    }
}

// ---------------- conversion kernels ----------------
__global__ void k_init(const float* __restrict__ hid){
    int i = blockIdx.x*blockDim.x + threadIdx.x;
    if (i < BH){
        float v = hid[i];
        g_prev0[i] = v; split_store(b_prev0_h, b_prev0_l, i, v);
    } else {
        int j = i - BH;
        float v = hid[i];
        g_prev1[j] = v; split_store(b_prev1_h, b_prev1_l, j, v);
    }
}

__global__ void k_split(const float* __restrict__ src,
                        __nv_bfloat16* __restrict__ hi, __nv_bfloat16* __restrict__ lo){
    size_t i4 = (size_t)blockIdx.x*blockDim.x + threadIdx.x;
    float4 v = *(const float4*)(src + i4*4);
    split_store4(hi, lo, i4*4, v);
}

__global__ void k_cvtRW(const float* __restrict__ Ur, const float* __restrict__ Uf,
                        const float* __restrict__ Uh, const float* __restrict__ Wr1,
                        const float* __restrict__ Wf1, const float* __restrict__ Wh1){
    const float* srcs[9] = {Ur, Uf, Uh, Wr1, Ur + HH, Wf1, Uf + HH, Wh1, Uh + HH};
    int m = blockIdx.y;
    size_t i4 = (size_t)blockIdx.x*blockDim.x + threadIdx.x;
    float4 v = *(const float4*)(srcs[m] + i4*4);
    split_store4(gRW_hi, gRW_lo, (size_t)m*HH + i4*4, v);
}

__global__ void k_cvtX(const int* __restrict__ toks, const float* __restrict__ emb){
    size_t i4 = (size_t)blockIdx.x*blockDim.x + threadIdx.x;
    int row  = (int)(i4 >> 8);
    int colq = (int)(i4 & 255);
    int tok  = toks[row];
    float4 v = *(const float4*)(emb + (size_t)tok*EMBD + colq*4);
    v.x *= SQRTE; v.y *= SQRTE; v.z *= SQRTE; v.w *= SQRTE;
    split_store4(gX_hi, gX_lo, i4*4, v);
}

__global__ void k_copy(float* __restrict__ dst){
    int i = blockIdx.x*blockDim.x + threadIdx.x;
    dst[i] = (i < BH) ? g_prev0[i] : g_prev1[i - BH];
}

// ---------------- launch ----------------
extern "C" void kernel_launch(void* const* d_in, const int* in_sizes, int n_in,
                              void* d_out, int out_size) {
    const int*   toks = (const int*)  d_in[0];
    const float* hid  = (const float*)d_in[1];
    const float* emb  = (const float*)d_in[2];
    const float* Win  = (const float*)d_in[3];
    const float* Wr1  = (const float*)d_in[4];
    const float* Wf1  = (const float*)d_in[5];
    const float* Wh1  = (const float*)d_in[6];
    const float* Ur   = (const float*)d_in[7];
    const float* br   = (const float*)d_in[8];
    const float* Uf   = (const float*)d_in[9];
    const float* bf   = (const float*)d_in[10];
    const float* Uh   = (const float*)d_in[11];
    const float* bh   = (const float*)d_in[12];
    const float* outW = (const float*)d_in[13];
    const float* outb = (const float*)d_in[14];
    float* out = (float*)d_out;

    const float *br0 = br, *br1 = br + HID;
    const float *bf0 = bf, *bf1 = bf + HID;
    const float *bh0 = bh, *bh1 = bh + HID;

    // real device addresses of __device__ globals used as kernel args
    void *pXh, *pXl, *pWinh, *pWinl, *pHh, *pHl, *pWh, *pWl, *pXin;
    cudaGetSymbolAddress(&pXh,  gX_hi);    cudaGetSymbolAddress(&pXl,  gX_lo);
    cudaGetSymbolAddress(&pWinh, gWin_hi); cudaGetSymbolAddress(&pWinl, gWin_lo);
    cudaGetSymbolAddress(&pHh,  gH_hi);    cudaGetSymbolAddress(&pHl,  gH_lo);
    cudaGetSymbolAddress(&pWh,  gW_hi);    cudaGetSymbolAddress(&pWl,  gW_lo);
    cudaGetSymbolAddress(&pXin, g_Xin);

    cudaFuncSetAttribute(k_mma128, cudaFuncAttributeMaxDynamicSharedMemorySize, OSMEM);
    cudaFuncSetAttribute(k_recur,  cudaFuncAttributeMaxDynamicSharedMemorySize, RSMEM);

    k_init<<<2*BH/256, 256>>>(hid);
    k_split<<<((size_t)VOCAB*HID/4)/256, 256>>>(outW, (__nv_bfloat16*)pWh, (__nv_bfloat16*)pWl);
    k_split<<<(HH/4)/256, 256>>>(Win, (__nv_bfloat16*)pWinh, (__nv_bfloat16*)pWinl);
    k_cvtRW<<<dim3(HH/4/256, 9), 256>>>(Ur, Uf, Uh, Wr1, Wf1, Wh1);
    k_cvtX<<<(SEQL*BATCH*EMBD/4)/256, 256>>>(toks, emb);
    // Xin = X @ Win^T  (4096 x 1024)
    k_mma128<<<dim3(32,8), 256, OSMEM>>>((__nv_bfloat16*)pXh, (__nv_bfloat16*)pXl,
                                         (__nv_bfloat16*)pWinh, (__nv_bfloat16*)pWinl,
                                         (float*)pXin, HID, nullptr);

    // whole recurrence: ONE persistent kernel
    k_recur<<<NCTA, 128, RSMEM>>>(br0, bf0, bh0, br1, bf1, bh1);

    // logits = H @ outW^T + outb
    k_mma128<<<dim3(32,250), 256, OSMEM>>>((__nv_bfloat16*)pHh, (__nv_bfloat16*)pHl,
                                           (__nv_bfloat16*)pWh, (__nv_bfloat16*)pWl,
                                           out, VOCAB, outb);

    if ((size_t)out_size >= LOGITS_N + 2*(size_t)BH)
        k_copy<<<2*BH/256, 256>>>(out + LOGITS_N);
}

// round 11
// speedup vs baseline: 2.1203x; 1.0325x over previous
#include <cuda_runtime.h>
#include <cuda_bf16.h>
#include <math.h>
#include <stdint.h>

// ---------------- problem constants ----------------
#define SEQL  64
#define BATCH 64
#define HID   1024
#define EMBD  1024
#define VOCAB 32000
#define BH    (BATCH*HID)            // 65536
#define LOGITS_N ((size_t)SEQL*BATCH*VOCAB)
#define SQRTE 32.0f
#define HH    (HID*HID)
#define NCTA  256                    // persistent grid, 2 CTAs/SM (<=2*148 -> co-resident)

typedef unsigned long long u64;

__device__ __forceinline__ float sigmf(float x){ return 1.0f/(1.0f + expf(-x)); }

// ---------------- smem / async-copy / mma helpers ----------------
__device__ __forceinline__ uint32_t smem_u32(const void* p){
    uint32_t a;
    asm("{ .reg .u64 t; cvta.to.shared.u64 t, %1; cvt.u32.u64 %0, t; }" : "=r"(a) : "l"(p));
    return a;
}
#define CP16(sa, gp) \
    asm volatile("cp.async.cg.shared.global [%0], [%1], 16;" :: "r"((uint32_t)(sa)), "l"(gp) : "memory")
#define CP_COMMIT() asm volatile("cp.async.commit_group;" ::: "memory")
#define CP_WAIT(n)  asm volatile("cp.async.wait_group %0;" :: "n"(n) : "memory")

__device__ __forceinline__ void ldsm4(uint32_t* r, uint32_t addr){
    asm volatile("ldmatrix.sync.aligned.m8n8.x4.shared.b16 {%0,%1,%2,%3}, [%4];"
        : "=r"(r[0]), "=r"(r[1]), "=r"(r[2]), "=r"(r[3]) : "r"(addr));
}
__device__ __forceinline__ void mma_bf16(float* d, const uint32_t* a, const uint32_t* b){
    asm volatile(
        "mma.sync.aligned.m16n8k16.row.col.f32.bf16.bf16.f32 "
        "{%0,%1,%2,%3}, {%4,%5,%6,%7}, {%8,%9}, {%0,%1,%2,%3};"
        : "+f"(d[0]), "+f"(d[1]), "+f"(d[2]), "+f"(d[3])
        : "r"(a[0]), "r"(a[1]), "r"(a[2]), "r"(a[3]), "r"(b[0]), "r"(b[1]));
}

// ---------------- device scratch ----------------
__device__ __align__(16) float g_Xin[SEQL*BH];
__device__ __align__(16) float g_prev0[BH];
__device__ __align__(16) float g_prev1[BH];
__device__ __align__(16) float g_z0[BH];
__device__ __align__(16) float g_z1[BH];
__device__ __align__(16) float g_part[32*BH];
// bf16 hi/lo activation operands
__device__ __align__(16) __nv_bfloat16 b_prev0_h[BH], b_prev0_l[BH];
__device__ __align__(16) __nv_bfloat16 b_prev1_h[BH], b_prev1_l[BH];
__device__ __align__(16) __nv_bfloat16 b_rp0_h[BH],   b_rp0_l[BH];
__device__ __align__(16) __nv_bfloat16 b_rp1_h[BH],   b_rp1_l[BH];
__device__ __align__(16) __nv_bfloat16 b_r0pre_h[BH], b_r0pre_l[BH];
__device__ __align__(16) __nv_bfloat16 b_f0pre_h[BH], b_f0pre_l[BH];
__device__ __align__(16) __nv_bfloat16 b_h0pre_h[BH], b_h0pre_l[BH];
// recurrence weights: 0=Ur0 1=Uf0 2=Uh0 3=Wr1 4=Ur1 5=Wf1 6=Uf1 7=Wh1 8=Uh1
__device__ __align__(16) __nv_bfloat16 gRW_hi[9*HH], gRW_lo[9*HH];
// k_xin operands
__device__ __align__(16) __nv_bfloat16 gX_hi[SEQL*BH], gX_lo[SEQL*BH];
__device__ __align__(16) __nv_bfloat16 gWin_hi[HH], gWin_lo[HH];
// output GEMM operands
__device__ __align__(16) __nv_bfloat16 gH_hi[SEQL*BH], gH_lo[SEQL*BH];
__device__ __align__(16) __nv_bfloat16 gW_hi[(size_t)VOCAB*HID], gW_lo[(size_t)VOCAB*HID];

// grid barrier state (monotone generation -> graph-replay safe)
__device__ unsigned g_barCnt = 0;
__device__ volatile unsigned g_barGen = 0;

__device__ __forceinline__ void gridbar(){
    __threadfence();                 // every thread's stores visible at L2
    __syncthreads();
    if (threadIdx.x == 0){
        unsigned g = g_barGen;
        if (atomicAdd(&g_barCnt, 1u) == NCTA - 1u){
            g_barCnt = 0;
            __threadfence();
            g_barGen = g + 1u;
        } else {
            while (g_barGen == g) { __nanosleep(32); }
        }
        __threadfence();             // acquire
    }
    __syncthreads();
}

__device__ __forceinline__ void split_store(__nv_bfloat16* hi, __nv_bfloat16* lo, size_t i, float v){
    __nv_bfloat16 h = __float2bfloat16_rn(v);
    hi[i] = h;
    lo[i] = __float2bfloat16_rn(v - __bfloat162float(h));
}
__device__ __forceinline__ void split_store4(__nv_bfloat16* hi, __nv_bfloat16* lo, size_t i, float4 v){
    __nv_bfloat162 h0 = __floats2bfloat162_rn(v.x, v.y);
    __nv_bfloat162 h1 = __floats2bfloat162_rn(v.z, v.w);
    __nv_bfloat162 l0 = __floats2bfloat162_rn(v.x - __low2float(h0),  v.y - __high2float(h0));
    __nv_bfloat162 l1 = __floats2bfloat162_rn(v.z - __low2float(h1),  v.w - __high2float(h1));
    *(__nv_bfloat162*)(hi + i)     = h0;
    *(__nv_bfloat162*)(hi + i + 2) = h1;
    *(__nv_bfloat162*)(lo + i)     = l0;
    *(__nv_bfloat162*)(lo + i + 2) = l1;
}
#define V4ADD(a,b) do{ (a).x+=(b).x; (a).y+=(b).y; (a).z+=(b).z; (a).w+=(b).w; }while(0)

// ---------------- 128x128 HMMA kernel (K=1024, split-bf16) ----------------
#define OSTAGE 40960
#define OSMEM  (2*OSTAGE)
#define OKIT   (HID/32)

__global__ void __launch_bounds__(256,1) k_mma128(
    const __nv_bfloat16* __restrict__ Ah, const __nv_bfloat16* __restrict__ Al,
    const __nv_bfloat16* __restrict__ Bh, const __nv_bfloat16* __restrict__ Bl,
    float* __restrict__ C, size_t ldc, const float* __restrict__ bias)
{
    extern __shared__ __align__(128) char smem[];
    const uint32_t sb = smem_u32(smem);
    const int tid  = threadIdx.x;
    const int lane = tid & 31;
    const int wid  = tid >> 5;
    const int wm   = wid >> 2;
    const int wn   = wid & 3;
    const int m0 = blockIdx.x * 128;
    const int n0 = blockIdx.y * 128;

    const int rowg = tid >> 2;
    const int seg  = tid & 3;
    const uint32_t soff = (uint32_t)rowg*80 + seg*16;
    const __nv_bfloat16* pAh = Ah + (size_t)(m0 + rowg)*HID + seg*8;
    const __nv_bfloat16* pAl = Al + (size_t)(m0 + rowg)*HID + seg*8;
    const __nv_bfloat16* pBh = Bh + (size_t)(n0 + rowg)*HID + seg*8;
    const __nv_bfloat16* pBl = Bl + (size_t)(n0 + rowg)*HID + seg*8;
    const size_t rstep = (size_t)64*HID;

    auto issue = [&](int buf, int k0){
        uint32_t s0 = sb + buf*OSTAGE;
        CP16(s0 +         soff,         pAh + k0);
        CP16(s0 +         soff + 64*80, pAh + k0 + rstep);
        CP16(s0 + 10240 + soff,         pAl + k0);
        CP16(s0 + 10240 + soff + 64*80, pAl + k0 + rstep);
        CP16(s0 + 20480 + soff,         pBh + k0);
        CP16(s0 + 20480 + soff + 64*80, pBh + k0 + rstep);
        CP16(s0 + 30720 + soff,         pBl + k0);
        CP16(s0 + 30720 + soff + 64*80, pBl + k0 + rstep);
    };

    const int rowA = (lane & 7) + ((lane >> 3) & 1)*8;
    const uint32_t aoff = (uint32_t)(wm*64 + rowA)*80 + (uint32_t)(lane >> 4)*16;
    const int rowB = (lane & 7) + (lane >> 4)*8;
    const uint32_t boff = 20480u + (uint32_t)(wn*32 + rowB)*80 + (uint32_t)((lane >> 3) & 1)*16;

    float acc[4][4][4];
#pragma unroll
    for (int mi = 0; mi < 4; mi++)
#pragma unroll
        for (int ni = 0; ni < 4; ni++)
#pragma unroll
            for (int r = 0; r < 4; r++) acc[mi][ni][r] = 0.f;

    issue(0, 0);
    CP_COMMIT();

    for (int s = 0; s < OKIT; s++){
        if (s + 1 < OKIT){ issue((s+1)&1, (s+1)*32); CP_COMMIT(); CP_WAIT(1); }
        else CP_WAIT(0);
        __syncthreads();

        const uint32_t st = sb + (s&1)*OSTAGE;
#pragma unroll
        for (int kk = 0; kk < 2; kk++){
            uint32_t aH[4][4], aL[4][4], bH[4][2], bL[4][2];
#pragma unroll
            for (int mi = 0; mi < 4; mi++){
                ldsm4(aH[mi], st +         aoff + mi*(16*80) + kk*32);
                ldsm4(aL[mi], st + 10240 + aoff + mi*(16*80) + kk*32);
            }
#pragma unroll
            for (int p = 0; p < 2; p++){
                uint32_t t[4];
                ldsm4(t, st +         boff + p*(16*80) + kk*32);
                bH[2*p][0]=t[0]; bH[2*p][1]=t[1]; bH[2*p+1][0]=t[2]; bH[2*p+1][1]=t[3];
                ldsm4(t, st + 10240 + boff + p*(16*80) + kk*32);
                bL[2*p][0]=t[0]; bL[2*p][1]=t[1]; bL[2*p+1][0]=t[2]; bL[2*p+1][1]=t[3];
            }
#pragma unroll
            for (int mi = 0; mi < 4; mi++)
#pragma unroll
                for (int ni = 0; ni < 4; ni++){
                    mma_bf16(acc[mi][ni], aH[mi], bH[ni]);
                    mma_bf16(acc[mi][ni], aH[mi], bL[ni]);
                    mma_bf16(acc[mi][ni], aL[mi], bH[ni]);
                }
        }
        __syncthreads();
    }

    const int mBase = m0 + wm*64 + (lane >> 2);
    const int nBase = n0 + wn*32 + (lane & 3)*2;
    float2 bv[4];
#pragma unroll
    for (int ni = 0; ni < 4; ni++)
        bv[ni] = bias ? *(const float2*)&bias[nBase + ni*8] : make_float2(0.f, 0.f);
#pragma unroll
    for (int mi = 0; mi < 4; mi++)
#pragma unroll
        for (int ni = 0; ni < 4; ni++)
#pragma unroll
            for (int r = 0; r < 2; r++){
                int m = mBase + mi*16 + r*8;
                float2 v = make_float2(acc[mi][ni][2*r] + bv[ni].x,
                                       acc[mi][ni][2*r+1] + bv[ni].y);
                *(float2*)&C[(size_t)m*ldc + nBase + ni*8] = v;
            }
}

// ---------------- recurrence HMMA core (64 x 128 tile) ----------------
#define RSTAGE 30720
#define RSMEM  (2*RSTAGE)

__device__ __noinline__ void mma_rec_core(
    const __nv_bfloat16* __restrict__ Ah, const __nv_bfloat16* __restrict__ Al,
    const __nv_bfloat16* __restrict__ Bh, const __nv_bfloat16* __restrict__ Bl,
    int k0, int kLen, float* __restrict__ Cp, int n0)
{
    extern __shared__ __align__(128) char smem[];
    const uint32_t sb = smem_u32(smem);
    const int tid  = threadIdx.x;
    const int lane = tid & 31;
    const int wn   = tid >> 5;

    auto issue = [&](int buf, int kofs){
        uint32_t s0 = sb + buf*RSTAGE;
#pragma unroll
        for (int i = 0; i < 2; i++){
            int idx = tid + i*128, row = idx >> 2, sg = idx & 3;
            uint32_t off = (uint32_t)row*80 + sg*16;
            size_t g = (size_t)row*HID + kofs + sg*8;
            CP16(s0 +        off, Ah + g);
            CP16(s0 + 5120 + off, Al + g);
        }
#pragma unroll
        for (int i = 0; i < 4; i++){
            int idx = tid + i*128, row = idx >> 2, sg = idx & 3;
            uint32_t off = (uint32_t)row*80 + sg*16;
            size_t g = (size_t)row*HID + kofs + sg*8;
            CP16(s0 + 10240 + off, Bh + g);
            CP16(s0 + 20480 + off, Bl + g);
        }
    };

    const int rowA = (lane & 7) + ((lane >> 3) & 1)*8;
    const uint32_t aoff = (uint32_t)rowA*80 + (uint32_t)(lane >> 4)*16;
    const int rowB = (lane & 7) + (lane >> 4)*8;
    const uint32_t boff = 10240u + (uint32_t)(wn*32 + rowB)*80 + (uint32_t)((lane >> 3) & 1)*16;

    float acc[4][4][4];
#pragma unroll
    for (int mi = 0; mi < 4; mi++)
#pragma unroll
        for (int ni = 0; ni < 4; ni++)
#pragma unroll
            for (int r = 0; r < 4; r++) acc[mi][ni][r] = 0.f;

    const int nst = kLen >> 5;
    issue(0, k0); CP_COMMIT();

    for (int s = 0; s < nst; s++){
        if (s + 1 < nst){ issue((s+1)&1, k0 + (s+1)*32); CP_COMMIT(); CP_WAIT(1); }
        else CP_WAIT(0);
        __syncthreads();

        const uint32_t st = sb + (s&1)*RSTAGE;
#pragma unroll
        for (int kk = 0; kk < 2; kk++){
            uint32_t aH[4][4], aL[4][4], bH[4][2], bL[4][2];
#pragma unroll
            for (int mi = 0; mi < 4; mi++){
                ldsm4(aH[mi], st +        aoff + mi*(16*80) + kk*32);
                ldsm4(aL[mi], st + 5120 + aoff + mi*(16*80) + kk*32);
            }
#pragma unroll
            for (int p = 0; p < 2; p++){
                uint32_t tr[4];
                ldsm4(tr, st +         boff + p*(16*80) + kk*32);
                bH[2*p][0]=tr[0]; bH[2*p][1]=tr[1]; bH[2*p+1][0]=tr[2]; bH[2*p+1][1]=tr[3];
                ldsm4(tr, st + 10240 + boff + p*(16*80) + kk*32);
                bL[2*p][0]=tr[0]; bL[2*p][1]=tr[1]; bL[2*p+1][0]=tr[2]; bL[2*p+1][1]=tr[3];
            }
#pragma unroll
            for (int mi = 0; mi < 4; mi++)
#pragma unroll
                for (int ni = 0; ni < 4; ni++){
                    mma_bf16(acc[mi][ni], aH[mi], bH[ni]);
                    mma_bf16(acc[mi][ni], aH[mi], bL[ni]);
                    mma_bf16(acc[mi][ni], aL[mi], bH[ni]);
                }
        }
        __syncthreads();
    }

    const int mBase = lane >> 2;
    const int nBase = n0 + wn*32 + (lane & 3)*2;
#pragma unroll
    for (int mi = 0; mi < 4; mi++)
#pragma unroll
        for (int ni = 0; ni < 4; ni++)
#pragma unroll
            for (int r = 0; r < 2; r++){
                int m = mBase + mi*16 + r*8;
                float2 v = make_float2(acc[mi][ni][2*r], acc[mi][ni][2*r+1]);
                *(float2*)&Cp[(size_t)m*HID + nBase + ni*8] = v;
            }
}

// job bodies ---------------------------------------------------------------
__device__ __forceinline__ void gates0_body(int nt, int gate, int ks){
    size_t wofs = (size_t)gate*HH + (size_t)nt*128*HID;
    mma_rec_core(b_prev0_h, b_prev0_l, gRW_hi + wofs, gRW_lo + wofs,
                 ks*128, 128, g_part + (size_t)(16 + gate*8 + ks)*BH, nt*128);
}
__device__ __forceinline__ void last_body(int nt, int ks){
    const __nv_bfloat16 *Ah, *Al; int widx, k0;
    if (ks < 8){ Ah = b_h0pre_h; Al = b_h0pre_l; widx = 7; k0 = ks*128; }
    else       { Ah = b_rp1_h;   Al = b_rp1_l;   widx = 8; k0 = (ks-8)*128; }
    size_t wofs = (size_t)widx*HH + (size_t)nt*128*HID;
    mma_rec_core(Ah, Al, gRW_hi + wofs, gRW_lo + wofs,
                 k0, 128, g_part + (size_t)ks*BH, nt*128);
}
__device__ __forceinline__ void mid_job(int j){   // j in [0,192)
    int job = j >> 6;          // 0,1,2
    int r   = j & 63;
    int nt  = r & 7;
    int ks  = r >> 3;          // 0..7
    const __nv_bfloat16 *Ah, *Al; int widx, k0, kLen;
    if (job == 0){ Ah = b_rp0_h; Al = b_rp0_l; widx = 2; k0 = ks*128; kLen = 128; }
    else {
        int wW = (job == 1) ? 3 : 5;
        int wU = (job == 1) ? 4 : 6;
        if (ks < 4){
            Ah = (job == 1) ? b_r0pre_h : b_f0pre_h;
            Al = (job == 1) ? b_r0pre_l : b_f0pre_l;
            widx = wW; k0 = ks*256;
        } else {
            Ah = b_prev1_h; Al = b_prev1_l;
            widx = wU; k0 = (ks-4)*256;
        }
        kLen = 256;
    }
    size_t wofs = (size_t)widx*HH + (size_t)nt*128*HID;
    mma_rec_core(Ah, Al, gRW_hi + wofs, gRW_lo + wofs,
                 k0, kLen, g_part + (size_t)(job*8 + ks)*BH, nt*128);
}

// fin device functions (1 float4 item per active thread; __ldcg bypasses stale L1)
__device__ __forceinline__ void fin0_one(size_t i, int t,
                                         const float* br0, const float* bf0){
    int n = (int)(i & (HID-1));
    float4 s0 = make_float4(0,0,0,0), s1 = s0;
#pragma unroll
    for (int ks = 0; ks < 8; ks++){
        float4 a = __ldcg((const float4*)&g_part[(size_t)(16+ks)*BH + i]); V4ADD(s0, a);
        float4 b = __ldcg((const float4*)&g_part[(size_t)(24+ks)*BH + i]); V4ADD(s1, b);
    }
    float4 xv = __ldcg((const float4*)&g_Xin[(size_t)t*BH + i]);
    float4 bR = *(const float4*)&br0[n];
    float4 bF = *(const float4*)&bf0[n];
    float4 p0 = __ldcg((const float4*)&g_prev0[i]);
    float4 rp = make_float4(xv.x+bR.x+s0.x, xv.y+bR.y+s0.y, xv.z+bR.z+s0.z, xv.w+bR.w+s0.w);
    float4 fp = make_float4(xv.x+bF.x+s1.x, xv.y+bF.y+s1.y, xv.z+bF.z+s1.z, xv.w+bF.w+s1.w);
    split_store4(b_r0pre_h, b_r0pre_l, i, rp);
    split_store4(b_f0pre_h, b_f0pre_l, i, fp);
    float4 rpv = make_float4(sigmf(rp.x)*p0.x, sigmf(rp.y)*p0.y, sigmf(rp.z)*p0.z, sigmf(rp.w)*p0.w);
    split_store4(b_rp0_h, b_rp0_l, i, rpv);
    *(float4*)&g_z0[i] = make_float4(sigmf(fp.x), sigmf(fp.y), sigmf(fp.z), sigmf(fp.w));
}

__device__ __forceinline__ void fin_mid_one(size_t i, int t, const float* bh0,
                                            const float* br1, const float* bf1){
    int n = (int)(i & (HID-1));
    float4 s0 = make_float4(0,0,0,0), s1 = s0, s2 = s0;
#pragma unroll
    for (int ks = 0; ks < 8; ks++){
        float4 a = __ldcg((const float4*)&g_part[(size_t)ks*BH + i]);      V4ADD(s0, a);
        float4 b = __ldcg((const float4*)&g_part[(size_t)(8+ks)*BH + i]);  V4ADD(s1, b);
        float4 c = __ldcg((const float4*)&g_part[(size_t)(16+ks)*BH + i]); V4ADD(s2, c);
    }
    float4 xv = __ldcg((const float4*)&g_Xin[(size_t)t*BH + i]);
    float4 bH = *(const float4*)&bh0[n];
    float4 ht = make_float4(xv.x+bH.x+s0.x, xv.y+bH.y+s0.y, xv.z+bH.z+s0.z, xv.w+bH.w+s0.w);
    float4 z  = __ldcg((const float4*)&g_z0[i]);
    float4 p0 = __ldcg((const float4*)&g_prev0[i]);
    float4 h0 = make_float4((1.f-z.x)*p0.x + z.x*tanhf(ht.x),
                            (1.f-z.y)*p0.y + z.y*tanhf(ht.y),
                            (1.f-z.z)*p0.z + z.z*tanhf(ht.z),
                            (1.f-z.w)*p0.w + z.w*tanhf(ht.w));
    *(float4*)&g_prev0[i] = h0;
    split_store4(b_prev0_h, b_prev0_l, i, h0);
    split_store4(b_h0pre_h, b_h0pre_l, i, ht);
    float4 bR = *(const float4*)&br1[n];
    float4 bF = *(const float4*)&bf1[n];
    float4 p1 = __ldcg((const float4*)&g_prev1[i]);
    float4 rp1 = make_float4(sigmf(s1.x+bR.x)*p1.x, sigmf(s1.y+bR.y)*p1.y,
                             sigmf(s1.z+bR.z)*p1.z, sigmf(s1.w+bR.w)*p1.w);
    split_store4(b_rp1_h, b_rp1_l, i, rp1);
    *(float4*)&g_z1[i] = make_float4(sigmf(s2.x+bF.x), sigmf(s2.y+bF.y),
                                     sigmf(s2.z+bF.z), sigmf(s2.w+bF.w));
}

__device__ __forceinline__ void finB_one(size_t i, int t, int dogates,
                                         const float* bh1, const float* br0, const float* bf0){
    int n = (int)(i & (HID-1));
    float4 s = make_float4(0,0,0,0);
#pragma unroll
    for (int ks = 0; ks < 16; ks++){
        float4 a = __ldcg((const float4*)&g_part[(size_t)ks*BH + i]); V4ADD(s, a);
    }
    float4 bH = *(const float4*)&bh1[n];
    float4 z  = __ldcg((const float4*)&g_z1[i]);
    float4 p1 = __ldcg((const float4*)&g_prev1[i]);
    float4 h1 = make_float4((1.f-z.x)*p1.x + z.x*tanhf(s.x+bH.x),
                            (1.f-z.y)*p1.y + z.y*tanhf(s.y+bH.y),
                            (1.f-z.z)*p1.z + z.z*tanhf(s.z+bH.z),
                            (1.f-z.w)*p1.w + z.w*tanhf(s.w+bH.w));
    *(float4*)&g_prev1[i] = h1;
    split_store4(b_prev1_h, b_prev1_l, i, h1);
    split_store4(gH_hi, gH_lo, (size_t)t*BH + i, h1);
    if (dogates){
        float4 s0 = make_float4(0,0,0,0), s1 = s0;
#pragma unroll
        for (int ks = 0; ks < 8; ks++){
            float4 a = __ldcg((const float4*)&g_part[(size_t)(16+ks)*BH + i]); V4ADD(s0, a);
            float4 b = __ldcg((const float4*)&g_part[(size_t)(24+ks)*BH + i]); V4ADD(s1, b);
        }
        float4 xv = __ldcg((const float4*)&g_Xin[(size_t)(t+1)*BH + i]);
        float4 bR = *(const float4*)&br0[n];
        float4 bF = *(const float4*)&bf0[n];
        float4 p0 = __ldcg((const float4*)&g_prev0[i]);
        float4 rp = make_float4(xv.x+bR.x+s0.x, xv.y+bR.y+s0.y, xv.z+bR.z+s0.z, xv.w+bR.w+s0.w);
        float4 fp = make_float4(xv.x+bF.x+s1.x, xv.y+bF.y+s1.y, xv.z+bF.z+s1.z, xv.w+bF.w+s1.w);
        split_store4(b_r0pre_h, b_r0pre_l, i, rp);
        split_store4(b_f0pre_h, b_f0pre_l, i, fp);
        float4 rpv = make_float4(sigmf(rp.x)*p0.x, sigmf(rp.y)*p0.y, sigmf(rp.z)*p0.z, sigmf(rp.w)*p0.w);
        split_store4(b_rp0_h, b_rp0_l, i, rpv);
        *(float4*)&g_z0[i] = make_float4(sigmf(fp.x), sigmf(fp.y), sigmf(fp.z), sigmf(fp.w));
    }
}

// ---------------- persistent recurrence kernel (256 CTAs, 2/SM) ----------------
__global__ void __launch_bounds__(128,2) k_recur(
    const float* __restrict__ br0, const float* __restrict__ bf0,
    const float* __restrict__ bh0, const float* __restrict__ br1,
    const float* __restrict__ bf1, const float* __restrict__ bh1)
{
    const int b   = blockIdx.x;
    const int tid = threadIdx.x;
    // fin items: 16384 float4 items over 256 CTAs x 64 threads
    const bool finT = (tid < 64);
    const size_t item = ((size_t)b*64 + tid)*4;

    // prologue: gates0 for t=0 (128 jobs on CTAs 0-127)
    if (b < 128) gates0_body((b>>3)&7, b>>6, b&7);
    gridbar();
    if (finT) fin0_one(item, 0, br0, bf0);
    gridbar();

    for (int t = 0; t < SEQL; t++){
        // phase mid: 192 jobs, 1 per CTA
        if (b < 192) mid_job(b);
        gridbar();
        if (finT) fin_mid_one(item, t, bh0, br1, bf1);
        gridbar();
        // phase B: 128 last jobs + 128 gates0(t+1) jobs, 1 per CTA
        if (b < 128) last_body(b >> 4, b & 15);
        else if (t < SEQL-1){
            int r = b - 128;
            gates0_body((r>>3)&7, r>>6, r&7);
        }
        gridbar();
        if (finT) finB_one(item, t, (t < SEQL-1) ? 1 : 0, bh1, br0, bf0);
        gridbar();
    }
}

// ---------------- conversion kernels ----------------
__global__ void k_init(const float* __restrict__ hid){
    int i = blockIdx.x*blockDim.x + threadIdx.x;
    if (i < BH){
        float v = hid[i];
        g_prev0[i] = v; split_store(b_prev0_h, b_prev0_l, i, v);
    } else {
        int j = i - BH;
        float v = hid[i];
        g_prev1[j] = v; split_store(b_prev1_h, b_prev1_l, j, v);
    }
}

__global__ void k_split(const float* __restrict__ src,
                        __nv_bfloat16* __restrict__ hi, __nv_bfloat16* __restrict__ lo){
    size_t i4 = (size_t)blockIdx.x*blockDim.x + threadIdx.x;
    float4 v = *(const float4*)(src + i4*4);
    split_store4(hi, lo, i4*4, v);
}

__global__ void k_cvtRW(const float* __restrict__ Ur, const float* __restrict__ Uf,
                        const float* __restrict__ Uh, const float* __restrict__ Wr1,
                        const float* __restrict__ Wf1, const float* __restrict__ Wh1){
    const float* srcs[9] = {Ur, Uf, Uh, Wr1, Ur + HH, Wf1, Uf + HH, Wh1, Uh + HH};
    int m = blockIdx.y;
    size_t i4 = (size_t)blockIdx.x*blockDim.x + threadIdx.x;
    float4 v = *(const float4*)(srcs[m] + i4*4);
    split_store4(gRW_hi, gRW_lo, (size_t)m*HH + i4*4, v);
}

__global__ void k_cvtX(const int* __restrict__ toks, const float* __restrict__ emb){
    size_t i4 = (size_t)blockIdx.x*blockDim.x + threadIdx.x;
    int row  = (int)(i4 >> 8);
    int colq = (int)(i4 & 255);
    int tok  = toks[row];
    float4 v = *(const float4*)(emb + (size_t)tok*EMBD + colq*4);
    v.x *= SQRTE; v.y *= SQRTE; v.z *= SQRTE; v.w *= SQRTE;
    split_store4(gX_hi, gX_lo, i4*4, v);
}

__global__ void k_copy(float* __restrict__ dst){
    int i = blockIdx.x*blockDim.x + threadIdx.x;
    dst[i] = (i < BH) ? g_prev0[i] : g_prev1[i - BH];
}

// ---------------- launch ----------------
extern "C" void kernel_launch(void* const* d_in, const int* in_sizes, int n_in,
                              void* d_out, int out_size) {
    const int*   toks = (const int*)  d_in[0];
    const float* hid  = (const float*)d_in[1];
    const float* emb  = (const float*)d_in[2];
    const float* Win  = (const float*)d_in[3];
    const float* Wr1  = (const float*)d_in[4];
    const float* Wf1  = (const float*)d_in[5];
    const float* Wh1  = (const float*)d_in[6];
    const float* Ur   = (const float*)d_in[7];
    const float* br   = (const float*)d_in[8];
    const float* Uf   = (const float*)d_in[9];
    const float* bf   = (const float*)d_in[10];
    const float* Uh   = (const float*)d_in[11];
    const float* bh   = (const float*)d_in[12];
    const float* outW = (const float*)d_in[13];
    const float* outb = (const float*)d_in[14];
    float* out = (float*)d_out;

    const float *br0 = br, *br1 = br + HID;
    const float *bf0 = bf, *bf1 = bf + HID;
    const float *bh0 = bh, *bh1 = bh + HID;

    // real device addresses of __device__ globals used as kernel args
    void *pXh, *pXl, *pWinh, *pWinl, *pHh, *pHl, *pWh, *pWl, *pXin;
    cudaGetSymbolAddress(&pXh,  gX_hi);    cudaGetSymbolAddress(&pXl,  gX_lo);
    cudaGetSymbolAddress(&pWinh, gWin_hi); cudaGetSymbolAddress(&pWinl, gWin_lo);
    cudaGetSymbolAddress(&pHh,  gH_hi);    cudaGetSymbolAddress(&pHl,  gH_lo);
    cudaGetSymbolAddress(&pWh,  gW_hi);    cudaGetSymbolAddress(&pWl,  gW_lo);
    cudaGetSymbolAddress(&pXin, g_Xin);

    cudaFuncSetAttribute(k_mma128, cudaFuncAttributeMaxDynamicSharedMemorySize, OSMEM);
    cudaFuncSetAttribute(k_recur,  cudaFuncAttributeMaxDynamicSharedMemorySize, RSMEM);

    k_init<<<2*BH/256, 256>>>(hid);
    k_split<<<((size_t)VOCAB*HID/4)/256, 256>>>(outW, (__nv_bfloat16*)pWh, (__nv_bfloat16*)pWl);
    k_split<<<(HH/4)/256, 256>>>(Win, (__nv_bfloat16*)pWinh, (__nv_bfloat16*)pWinl);
    k_cvtRW<<<dim3(HH/4/256, 9), 256>>>(Ur, Uf, Uh, Wr1, Wf1, Wh1);
    k_cvtX<<<(SEQL*BATCH*EMBD/4)/256, 256>>>(toks, emb);
    // Xin = X @ Win^T  (4096 x 1024)
    k_mma128<<<dim3(32,8), 256, OSMEM>>>((__nv_bfloat16*)pXh, (__nv_bfloat16*)pXl,
                                         (__nv_bfloat16*)pWinh, (__nv_bfloat16*)pWinl,
                                         (float*)pXin, HID, nullptr);

    // whole recurrence: ONE persistent kernel, 256 co-resident CTAs
    k_recur<<<NCTA, 128, RSMEM>>>(br0, bf0, bh0, br1, bf1, bh1);

    // logits = H @ outW^T + outb
    k_mma128<<<dim3(32,250), 256, OSMEM>>>((__nv_bfloat16*)pHh, (__nv_bfloat16*)pHl,
                                           (__nv_bfloat16*)pWh, (__nv_bfloat16*)pWl,
                                           out, VOCAB, outb);

    if ((size_t)out_size >= LOGITS_N + 2*(size_t)BH)
        k_copy<<<2*BH/256, 256>>>(out + LOGITS_N);
}